// round 12
// baseline (speedup 1.0000x reference)
#include <cuda_runtime.h>
#include <cuda_bf16.h>
#include <cstdint>

#define B_  8
#define L_  1024
#define D_  1024
#define H_  16
#define DK_ 64
#define M_  (B_*L_)   // 8192

// ---------------- scratch (device globals) ----------------
__device__ __nv_bfloat16 g_qHi[M_*D_], g_qLo[M_*D_];   // [B,H,L,64]
__device__ __nv_bfloat16 g_kHi[M_*D_], g_kLo[M_*D_];
__device__ __nv_bfloat16 g_vHi[M_*D_], g_vLo[M_*D_];
__device__ __nv_bfloat16 g_pHi[134217728], g_pLo[134217728];   // P (attn) bf16 hi/lo
__device__ float g_outs[M_*D_];
__device__ __nv_bfloat16 g_hidHi[M_*D_], g_hidLo[M_*D_];
__device__ __nv_bfloat16 g_keyHi[M_*D_], g_keyLo[M_*D_];
__device__ __nv_bfloat16 g_cvHi [M_*D_], g_cvLo [M_*D_];
__device__ __nv_bfloat16 g_ctxHi[M_*D_], g_ctxLo[M_*D_];
__device__ __nv_bfloat16 g_WqHi[D_*D_], g_WqLo[D_*D_];
__device__ __nv_bfloat16 g_WkHi[D_*D_], g_WkLo[D_*D_];
__device__ __nv_bfloat16 g_WvHi[D_*D_], g_WvLo[D_*D_];
__device__ __nv_bfloat16 g_WoHi[D_*D_], g_WoLo[D_*D_];

// ---------------- helpers ----------------
__device__ __forceinline__ uint32_t smem_u32(const void* p) {
    return (uint32_t)__cvta_generic_to_shared((void*)p);
}
#define CP_COMMIT() asm volatile("cp.async.commit_group;" ::: "memory")
#define CP_WAIT0()  asm volatile("cp.async.wait_group 0;" ::: "memory")
#define CP_WAIT1()  asm volatile("cp.async.wait_group 1;" ::: "memory")
__device__ __forceinline__ void cp16(uint32_t dst, const void* src) {
    asm volatile("cp.async.cg.shared.global [%0], [%1], 16;" :: "r"(dst), "l"(src));
}
__device__ __forceinline__ void ldsm4(uint32_t* r, uint32_t a) {
    asm volatile("ldmatrix.sync.aligned.m8n8.x4.shared.b16 {%0,%1,%2,%3}, [%4];"
        : "=r"(r[0]), "=r"(r[1]), "=r"(r[2]), "=r"(r[3]) : "r"(a));
}
__device__ __forceinline__ void ldsm4t(uint32_t* r, uint32_t a) {
    asm volatile("ldmatrix.sync.aligned.m8n8.x4.trans.shared.b16 {%0,%1,%2,%3}, [%4];"
        : "=r"(r[0]), "=r"(r[1]), "=r"(r[2]), "=r"(r[3]) : "r"(a));
}
__device__ __forceinline__ void mma_bf16(float* c, const uint32_t* a, const uint32_t* b) {
    asm volatile("mma.sync.aligned.m16n8k16.row.col.f32.bf16.bf16.f32 "
        "{%0,%1,%2,%3}, {%4,%5,%6,%7}, {%8,%9}, {%0,%1,%2,%3};"
        : "+f"(c[0]), "+f"(c[1]), "+f"(c[2]), "+f"(c[3])
        : "r"(a[0]), "r"(a[1]), "r"(a[2]), "r"(a[3]), "r"(b[0]), "r"(b[1]));
}
__device__ __forceinline__ void hilo_pack(float a, float b, uint32_t& hi, uint32_t& lo) {
    __nv_bfloat16 ha = __float2bfloat16(a), hb = __float2bfloat16(b);
    __nv_bfloat16 la = __float2bfloat16(a - __bfloat162float(ha));
    __nv_bfloat16 lb = __float2bfloat16(b - __bfloat162float(hb));
    hi = (uint32_t)__bfloat16_as_ushort(ha) | ((uint32_t)__bfloat16_as_ushort(hb) << 16);
    lo = (uint32_t)__bfloat16_as_ushort(la) | ((uint32_t)__bfloat16_as_ushort(lb) << 16);
}

// ---------------- prep: fp32 -> bf16 hi/lo (batched) ----------------
struct __align__(8) bf4 { __nv_bfloat16 x, y, z, w; };
__global__ void split3_kernel(const float4* __restrict__ X0, const float4* __restrict__ X1,
                              const float4* __restrict__ X2,
                              bf4* __restrict__ H0, bf4* __restrict__ L0,
                              bf4* __restrict__ H1, bf4* __restrict__ L1,
                              bf4* __restrict__ H2, bf4* __restrict__ L2, int n4)
{
    const float4* X; bf4 *Hi, *Lo;
    if (blockIdx.y == 0)      { X = X0; Hi = H0; Lo = L0; }
    else if (blockIdx.y == 1) { X = X1; Hi = H1; Lo = L1; }
    else                      { X = X2; Hi = H2; Lo = L2; }
    int i = blockIdx.x * 256 + threadIdx.x;
    if (i >= n4) return;
    float4 v = X[i];
    bf4 h, l;
    h.x = __float2bfloat16(v.x); l.x = __float2bfloat16(v.x - __bfloat162float(h.x));
    h.y = __float2bfloat16(v.y); l.y = __float2bfloat16(v.y - __bfloat162float(h.y));
    h.z = __float2bfloat16(v.z); l.z = __float2bfloat16(v.z - __bfloat162float(h.z));
    h.w = __float2bfloat16(v.w); l.w = __float2bfloat16(v.w - __bfloat162float(h.w));
    Hi[i] = h; Lo[i] = l;
}
__global__ void tsplit4_kernel(const float* __restrict__ W0, const float* __restrict__ W1,
                               const float* __restrict__ W2, const float* __restrict__ W3,
                               __nv_bfloat16* __restrict__ H0, __nv_bfloat16* __restrict__ L0,
                               __nv_bfloat16* __restrict__ H1, __nv_bfloat16* __restrict__ L1,
                               __nv_bfloat16* __restrict__ H2, __nv_bfloat16* __restrict__ L2,
                               __nv_bfloat16* __restrict__ H3, __nv_bfloat16* __restrict__ L3)
{
    const float* W; __nv_bfloat16 *Hi, *Lo;
    int z = blockIdx.z;
    if (z == 0)      { W = W0; Hi = H0; Lo = L0; }
    else if (z == 1) { W = W1; Hi = H1; Lo = L1; }
    else if (z == 2) { W = W2; Hi = H2; Lo = L2; }
    else             { W = W3; Hi = H3; Lo = L3; }
    __shared__ float t[32][33];
    int bx = blockIdx.x * 32, by = blockIdx.y * 32;
    int x = threadIdx.x, y = threadIdx.y;
#pragma unroll
    for (int i = 0; i < 32; i += 8)
        t[y + i][x] = W[(size_t)(by + y + i) * D_ + bx + x];
    __syncthreads();
#pragma unroll
    for (int i = 0; i < 32; i += 8) {
        float v = t[x][y + i];
        __nv_bfloat16 h = __float2bfloat16(v);
        __nv_bfloat16 l = __float2bfloat16(v - __bfloat162float(h));
        size_t o = (size_t)(bx + y + i) * D_ + by + x;
        Hi[o] = h; Lo[o] = l;
    }
}

// ---------------- HMMA GEMM (R3 config): 128x128 tile, 256 threads ----------------
#define HG_ST 40960u
template <int MODE>
__device__ __forceinline__
void hgemm_body(const __nv_bfloat16* __restrict__ AHi, const __nv_bfloat16* __restrict__ ALo,
                const __nv_bfloat16* __restrict__ BHi, const __nv_bfloat16* __restrict__ BLo,
                const float* __restrict__ bias,
                float* __restrict__ C, __nv_bfloat16* __restrict__ CHi, __nv_bfloat16* __restrict__ CLo,
                char* smc)
{
    const int tid = threadIdx.x, lane = tid & 31, wid = tid >> 5;
    const int wm = wid >> 2, wn = wid & 3;
    const int n0 = blockIdx.x * 128, m0 = blockIdx.y * 128;
    const uint32_t sb = smem_u32(smc);

    const int lr = tid >> 2, lc = tid & 3;
    const int arow = wm * 64 + (lane & 15);
    const uint32_t akb = (lane >> 4) * 16;
    const int bn8 = (lane & 16) ? 8 : 0;
    const uint32_t bkh = (lane & 8) ? 16 : 0;
    const int br = lane & 7;

    float acc[4][4][4];
#pragma unroll
    for (int i = 0; i < 4; i++)
#pragma unroll
        for (int j = 0; j < 4; j++)
#pragma unroll
            for (int q = 0; q < 4; q++) acc[i][j][q] = 0.f;

    auto load_stage = [&](int s, int buf) {
        uint32_t base = sb + buf * HG_ST;
        int k0 = s * 32;
#pragma unroll
        for (int half = 0; half < 2; half++) {
            int row = lr + half * 64;
            uint32_t doff = row * 80 + lc * 16;
            cp16(base + doff,          AHi + (size_t)(m0 + row) * D_ + k0 + lc * 8);
            cp16(base + 10240 + doff,  ALo + (size_t)(m0 + row) * D_ + k0 + lc * 8);
            cp16(base + 20480 + doff,  BHi + (size_t)(n0 + row) * D_ + k0 + lc * 8);
            cp16(base + 30720 + doff,  BLo + (size_t)(n0 + row) * D_ + k0 + lc * 8);
        }
    };

    load_stage(0, 0); CP_COMMIT();

    for (int s = 0; s < 32; s++) {
        if (s < 31) { load_stage(s + 1, (s + 1) & 1); CP_COMMIT(); CP_WAIT1(); }
        else        { CP_WAIT0(); }
        __syncthreads();
        uint32_t aHiB = sb + (s & 1) * HG_ST;
        uint32_t aLoB = aHiB + 10240, bHiB = aHiB + 20480, bLoB = aHiB + 30720;
#pragma unroll
        for (int h = 0; h < 2; h++) {
            uint32_t bhi[2][4], blo[2][4];
#pragma unroll
            for (int g = 0; g < 2; g++) {
                uint32_t ba = (uint32_t)(wn * 32 + g * 16 + bn8 + br) * 80 + h * 32 + bkh;
                ldsm4(bhi[g], bHiB + ba);
                ldsm4(blo[g], bLoB + ba);
            }
#pragma unroll
            for (int mf = 0; mf < 4; mf++) {
                uint32_t ah[4], al[4];
                uint32_t aa = (uint32_t)(arow + mf * 16) * 80 + h * 32 + akb;
                ldsm4(ah, aHiB + aa);
                ldsm4(al, aLoB + aa);
#pragma unroll
                for (int g = 0; g < 2; g++)
#pragma unroll
                    for (int j = 0; j < 2; j++) {
                        float* c = acc[mf][g * 2 + j];
                        mma_bf16(c, ah, &bhi[g][j * 2]);
                        mma_bf16(c, ah, &blo[g][j * 2]);
                        mma_bf16(c, al, &bhi[g][j * 2]);
                    }
            }
        }
        __syncthreads();
    }

#pragma unroll
    for (int mf = 0; mf < 4; mf++)
#pragma unroll
        for (int nf = 0; nf < 4; nf++) {
            int col = n0 + wn * 32 + nf * 8 + (lane & 3) * 2;
            float b0 = __ldg(bias + col), b1 = __ldg(bias + col + 1);
            int r0 = m0 + wm * 64 + mf * 16 + (lane >> 2);
#pragma unroll
            for (int half = 0; half < 2; half++) {
                int r = r0 + half * 8;
                float v0 = acc[mf][nf][half * 2 + 0] + b0;
                float v1 = acc[mf][nf][half * 2 + 1] + b1;
                if (MODE == 0) {
                    *(float2*)(C + (size_t)r * D_ + col) = make_float2(v0, v1);
                } else {
                    int hh = col >> 6, d = col & 63;
                    int bb = r >> 10, l = r & 1023;
                    size_t dst = (((size_t)(bb * H_ + hh) * L_ + l) * DK_) + d;
                    uint32_t hi, lo;
                    hilo_pack(v0, v1, hi, lo);
                    *(uint32_t*)(CHi + dst) = hi;
                    *(uint32_t*)(CLo + dst) = lo;
                }
            }
        }
}

__global__ __launch_bounds__(256)
void hgemm_qkv(const __nv_bfloat16* hidHi, const __nv_bfloat16* hidLo,
               const __nv_bfloat16* keyHi, const __nv_bfloat16* keyLo,
               const __nv_bfloat16* cvHi,  const __nv_bfloat16* cvLo,
               const __nv_bfloat16* WqHi, const __nv_bfloat16* WqLo,
               const __nv_bfloat16* WkHi, const __nv_bfloat16* WkLo,
               const __nv_bfloat16* WvHi, const __nv_bfloat16* WvLo,
               const float* bq, const float* bk, const float* bv,
               __nv_bfloat16* qHi, __nv_bfloat16* qLo,
               __nv_bfloat16* kHi, __nv_bfloat16* kLo,
               __nv_bfloat16* vHi, __nv_bfloat16* vLo)
{
    extern __shared__ char smc[];
    const __nv_bfloat16 *AHi, *ALo, *BHi, *BLo;
    const float* bias;
    __nv_bfloat16 *CHi, *CLo;
    int z = blockIdx.z;
    if (z == 0)      { AHi = hidHi; ALo = hidLo; BHi = WqHi; BLo = WqLo; bias = bq; CHi = qHi; CLo = qLo; }
    else if (z == 1) { AHi = keyHi; ALo = keyLo; BHi = WkHi; BLo = WkLo; bias = bk; CHi = kHi; CLo = kLo; }
    else             { AHi = cvHi;  ALo = cvLo;  BHi = WvHi; BLo = WvLo; bias = bv; CHi = vHi; CLo = vLo; }
    hgemm_body<1>(AHi, ALo, BHi, BLo, bias, nullptr, CHi, CLo, smc);
}

__global__ __launch_bounds__(256)
void hgemm_out(const __nv_bfloat16* AHi, const __nv_bfloat16* ALo,
               const __nv_bfloat16* BHi, const __nv_bfloat16* BLo,
               const float* bias, float* C)
{
    extern __shared__ char smc[];
    hgemm_body<0>(AHi, ALo, BHi, BLo, bias, C, nullptr, nullptr, smc);
}

// ---------------- scores (Q hoisted) + softmax + bf16 hi/lo P emit ----------------
#define SC_SMEM 215168u
__global__ __launch_bounds__(256)
void scores_mma(const __nv_bfloat16* __restrict__ QHi, const __nv_bfloat16* __restrict__ QLo,
                const __nv_bfloat16* __restrict__ KHi, const __nv_bfloat16* __restrict__ KLo,
                float* __restrict__ attn,
                __nv_bfloat16* __restrict__ PHi, __nv_bfloat16* __restrict__ PLo)
{
    extern __shared__ char smc[];
    const int tid = threadIdx.x, lane = tid & 31, wid = tid >> 5;
    const int wm = wid >> 2, wn = wid & 3;
    const int bh = blockIdx.y, q0 = blockIdx.x * 32;
    const uint32_t sb = smem_u32(smc);
    float* Ss = (float*)(smc + 82944);
    float* sinv = (float*)(smc + 215040);

    {
        int row = tid >> 3, ch = tid & 7;
        const size_t src = ((size_t)bh * L_ + q0 + row) * DK_ + ch * 8;
        cp16(sb + row * 144 + ch * 16, QHi + src);
        cp16(sb + 4608 + row * 144 + ch * 16, QLo + src);
    }
    auto loadK = [&](int cc, int buf) {
        uint32_t base = sb + 9216 + buf * 36864;
#pragma unroll
        for (int i = 0; i < 4; i++) {
            int idx = tid + i * 256;
            int row = idx >> 3, ch = idx & 7;
            const size_t src = ((size_t)bh * L_ + cc * 128 + row) * DK_ + ch * 8;
            cp16(base + row * 144 + ch * 16, KHi + src);
            cp16(base + 18432 + row * 144 + ch * 16, KLo + src);
        }
    };
    loadK(0, 0); CP_COMMIT();
    CP_WAIT0();
    __syncthreads();     // Q + K0 resident

    const uint32_t akb = (lane >> 4) * 16;
    const int bn8 = (lane & 16) ? 8 : 0;
    const uint32_t bkh = (lane & 8) ? 16 : 0;
    const int br = lane & 7;

    // hoist Q fragments (static across all K chunks)
    uint32_t qh[4][4], ql[4][4];
#pragma unroll
    for (int h = 0; h < 4; h++) {
        uint32_t aa = (uint32_t)(wm * 16 + (lane & 15)) * 144 + h * 32 + akb;
        ldsm4(qh[h], sb + aa);
        ldsm4(ql[h], sb + 4608 + aa);
    }

    for (int cc = 0; cc < 8; cc++) {
        if (cc < 7) { loadK(cc + 1, (cc + 1) & 1); CP_COMMIT(); CP_WAIT1(); }
        else        { CP_WAIT0(); }
        __syncthreads();
        uint32_t kHiB = sb + 9216 + (cc & 1) * 36864;
        uint32_t kLoB = kHiB + 18432;
        float acc[4][4];
#pragma unroll
        for (int i = 0; i < 4; i++)
#pragma unroll
            for (int q = 0; q < 4; q++) acc[i][q] = 0.f;
#pragma unroll
        for (int h = 0; h < 4; h++) {
            uint32_t bhi[2][4], blo[2][4];
#pragma unroll
            for (int g = 0; g < 2; g++) {
                uint32_t ba = (uint32_t)(wn * 32 + g * 16 + bn8 + br) * 144 + h * 32 + bkh;
                ldsm4(bhi[g], kHiB + ba);
                ldsm4(blo[g], kLoB + ba);
            }
#pragma unroll
            for (int g = 0; g < 2; g++)
#pragma unroll
                for (int j = 0; j < 2; j++) {
                    float* c = acc[g * 2 + j];
                    mma_bf16(c, qh[h], &bhi[g][j * 2]);
                    mma_bf16(c, qh[h], &blo[g][j * 2]);
                    mma_bf16(c, ql[h], &bhi[g][j * 2]);
                }
        }
#pragma unroll
        for (int nf = 0; nf < 4; nf++) {
            int col = cc * 128 + wn * 32 + nf * 8 + (lane & 3) * 2;
            int row = wm * 16 + (lane >> 2);
            *(float2*)(Ss + (size_t)row * 1032 + col) =
                make_float2(acc[nf][0] * 0.125f, acc[nf][1] * 0.125f);
            *(float2*)(Ss + (size_t)(row + 8) * 1032 + col) =
                make_float2(acc[nf][2] * 0.125f, acc[nf][3] * 0.125f);
        }
        __syncthreads();
    }

    int r = tid >> 3, g = tid & 7;
    float m = -1e30f;
    for (int c = g; c < 1024; c += 8) m = fmaxf(m, Ss[r * 1032 + c]);
#pragma unroll
    for (int o = 4; o; o >>= 1) m = fmaxf(m, __shfl_xor_sync(0xffffffffu, m, o));
    float s = 0.f;
    for (int c = g; c < 1024; c += 8) {
        float e = __expf(Ss[r * 1032 + c] - m);
        s += e;
        Ss[r * 1032 + c] = e;
    }
#pragma unroll
    for (int o = 4; o; o >>= 1) s += __shfl_xor_sync(0xffffffffu, s, o);
    if (g == 0) sinv[r] = 1.f / s;
    __syncthreads();

    // epilogue: normalized P -> fp32 attn (optional) + bf16 hi/lo P (always)
    float* Ap = attn ? attn + ((size_t)bh * L_ + q0) * L_ : nullptr;
    __nv_bfloat16* PhP = PHi + ((size_t)bh * L_ + q0) * L_;
    __nv_bfloat16* PlP = PLo + ((size_t)bh * L_ + q0) * L_;
    for (int idx = tid; idx < 32 * 1024 / 4; idx += 256) {
        int rr = idx >> 8, c4 = idx & 255;
        float inv = sinv[rr];
        float4 v;
        v.x = Ss[rr * 1032 + c4 * 4 + 0] * inv;
        v.y = Ss[rr * 1032 + c4 * 4 + 1] * inv;
        v.z = Ss[rr * 1032 + c4 * 4 + 2] * inv;
        v.w = Ss[rr * 1032 + c4 * 4 + 3] * inv;
        if (Ap) ((float4*)Ap)[idx] = v;
        uint32_t h0, l0, h1, l1;
        hilo_pack(v.x, v.y, h0, l0);
        hilo_pack(v.z, v.w, h1, l1);
        ((uint2*)PhP)[idx] = make_uint2(h0, h1);
        ((uint2*)PlP)[idx] = make_uint2(l0, l1);
    }
}

// ---------------- ctx = P @ V (HMMA): P bf16 hi/lo via cp.async, no conversion ----------------
// smem: Phi 0 (128*144) | Plo 18432 | Vhi 36864 (64*144) | Vlo 46080 ; total 55296
__global__ __launch_bounds__(256)
void ctx_mma(const __nv_bfloat16* __restrict__ PHi, const __nv_bfloat16* __restrict__ PLo,
             const __nv_bfloat16* __restrict__ VHi, const __nv_bfloat16* __restrict__ VLo,
             __nv_bfloat16* __restrict__ CHi, __nv_bfloat16* __restrict__ CLo)
{
    extern __shared__ char smc[];
    const int tid = threadIdx.x, lane = tid & 31, wid = tid >> 5;
    const int wm = wid >> 1, wn = wid & 1;
    const int bh = blockIdx.y, q0 = blockIdx.x * 128;
    const int b = bh >> 4, hh = bh & 15;
    const uint32_t sb = smem_u32(smc);

    float acc[2][4][4];
#pragma unroll
    for (int i = 0; i < 2; i++)
#pragma unroll
        for (int j = 0; j < 4; j++)
#pragma unroll
            for (int q = 0; q < 4; q++) acc[i][j][q] = 0.f;

    const uint32_t akb = (lane >> 4) * 16;
    const int vkoff = ((lane & 8) ? 8 : 0) + (lane & 7);
    const int vdoff = (lane & 16) ? 8 : 0;

    for (int k0 = 0; k0 < L_; k0 += 64) {
        // V chunk: 64 rows x 64 cols bf16 (hi+lo)
#pragma unroll
        for (int i = 0; i < 2; i++) {
            int idx = tid + i * 256;
            int row = idx >> 3, ch = idx & 7;
            const size_t src = ((size_t)bh * L_ + k0 + row) * DK_ + ch * 8;
            cp16(sb + 36864 + row * 144 + ch * 16, VHi + src);
            cp16(sb + 46080 + row * 144 + ch * 16, VLo + src);
        }
        // P chunk: 128 q-rows x 64 k bf16 (hi+lo) straight from gmem
#pragma unroll
        for (int i = 0; i < 4; i++) {
            int idx = tid + i * 256;
            int row = idx >> 3, ch = idx & 7;
            const size_t src = ((size_t)bh * L_ + q0 + row) * L_ + k0 + ch * 8;
            cp16(sb + row * 144 + ch * 16, PHi + src);
            cp16(sb + 18432 + row * 144 + ch * 16, PLo + src);
        }
        CP_COMMIT();
        CP_WAIT0();
        __syncthreads();
#pragma unroll
        for (int h = 0; h < 4; h++) {
            uint32_t vhi[2][4], vlo[2][4];
#pragma unroll
            for (int g = 0; g < 2; g++) {
                uint32_t va = (uint32_t)(h * 16 + vkoff) * 144
                            + (uint32_t)(wn * 32 + g * 16 + vdoff) * 2;
                ldsm4t(vhi[g], sb + 36864 + va);
                ldsm4t(vlo[g], sb + 46080 + va);
            }
#pragma unroll
            for (int mf = 0; mf < 2; mf++) {
                uint32_t ah[4], al[4];
                uint32_t aa = (uint32_t)(wm * 32 + mf * 16 + (lane & 15)) * 144 + h * 32 + akb;
                ldsm4(ah, sb + aa);
                ldsm4(al, sb + 18432 + aa);
#pragma unroll
                for (int g = 0; g < 2; g++)
#pragma unroll
                    for (int j = 0; j < 2; j++) {
                        float* c = acc[mf][g * 2 + j];
                        mma_bf16(c, ah, &vhi[g][j * 2]);
                        mma_bf16(c, ah, &vlo[g][j * 2]);
                        mma_bf16(c, al, &vhi[g][j * 2]);
                    }
            }
        }
        __syncthreads();
    }

#pragma unroll
    for (int mf = 0; mf < 2; mf++)
#pragma unroll
        for (int nf = 0; nf < 4; nf++) {
            int d = wn * 32 + nf * 8 + (lane & 3) * 2;
            int q = q0 + wm * 32 + mf * 16 + (lane >> 2);
#pragma unroll
            for (int half = 0; half < 2; half++) {
                int qq = q + half * 8;
                size_t dst = ((size_t)(b * L_ + qq)) * D_ + hh * DK_ + d;
                uint32_t hi, lo;
                hilo_pack(acc[mf][nf][half * 2 + 0], acc[mf][nf][half * 2 + 1], hi, lo);
                *(uint32_t*)(CHi + dst) = hi;
                *(uint32_t*)(CLo + dst) = lo;
            }
        }
}

// ---------------------------------------------------------------------------
extern "C" void kernel_launch(void* const* d_in, const int* in_sizes, int n_in,
                              void* d_out, int out_size)
{
    const float* hidden = (const float*)d_in[0];
    const float* key    = (const float*)d_in[1];
    const float* ctxv   = (const float*)d_in[2];
    const float* Wq = (const float*)d_in[3];
    const float* bq = (const float*)d_in[4];
    const float* Wk = (const float*)d_in[5];
    const float* bk = (const float*)d_in[6];
    const float* Wv = (const float*)d_in[7];
    const float* bv = (const float*)d_in[8];
    const float* Wo = (const float*)d_in[9];
    const float* bo = (const float*)d_in[10];

    float *op;
    cudaGetSymbolAddress((void**)&op, g_outs);
    __nv_bfloat16 *qHi,*qLo,*kHi,*kLo,*vHi,*vLo,*pHi,*pLo;
    cudaGetSymbolAddress((void**)&qHi, g_qHi); cudaGetSymbolAddress((void**)&qLo, g_qLo);
    cudaGetSymbolAddress((void**)&kHi, g_kHi); cudaGetSymbolAddress((void**)&kLo, g_kLo);
    cudaGetSymbolAddress((void**)&vHi, g_vHi); cudaGetSymbolAddress((void**)&vLo, g_vLo);
    cudaGetSymbolAddress((void**)&pHi, g_pHi); cudaGetSymbolAddress((void**)&pLo, g_pLo);
    __nv_bfloat16 *hidHi,*hidLo,*keyHi,*keyLo,*cvHi,*cvLo,*ctxHi,*ctxLo;
    cudaGetSymbolAddress((void**)&hidHi, g_hidHi); cudaGetSymbolAddress((void**)&hidLo, g_hidLo);
    cudaGetSymbolAddress((void**)&keyHi, g_keyHi); cudaGetSymbolAddress((void**)&keyLo, g_keyLo);
    cudaGetSymbolAddress((void**)&cvHi,  g_cvHi);  cudaGetSymbolAddress((void**)&cvLo,  g_cvLo);
    cudaGetSymbolAddress((void**)&ctxHi, g_ctxHi); cudaGetSymbolAddress((void**)&ctxLo, g_ctxLo);
    __nv_bfloat16 *WqHi,*WqLo,*WkHi,*WkLo,*WvHi,*WvLo,*WoHi,*WoLo;
    cudaGetSymbolAddress((void**)&WqHi, g_WqHi); cudaGetSymbolAddress((void**)&WqLo, g_WqLo);
    cudaGetSymbolAddress((void**)&WkHi, g_WkHi); cudaGetSymbolAddress((void**)&WkLo, g_WkLo);
    cudaGetSymbolAddress((void**)&WvHi, g_WvHi); cudaGetSymbolAddress((void**)&WvLo, g_WvLo);
    cudaGetSymbolAddress((void**)&WoHi, g_WoHi); cudaGetSymbolAddress((void**)&WoLo, g_WoLo);

    const size_t out_elems  = (size_t)B_ * L_ * D_;
    const size_t attn_elems = (size_t)B_ * H_ * L_ * L_;
    float* outp;
    float* attnp;   // nullptr -> fp32 attn not needed
    if ((size_t)out_size >= out_elems + attn_elems) {
        outp  = (float*)d_out;
        attnp = (float*)d_out + out_elems;
    } else if ((size_t)out_size == attn_elems) {
        outp  = op;
        attnp = (float*)d_out;
    } else {
        outp  = (float*)d_out;
        attnp = nullptr;          // attn not checked; skip fp32 write
    }

    cudaFuncSetAttribute(hgemm_qkv, cudaFuncAttributeMaxDynamicSharedMemorySize, 2 * HG_ST);
    cudaFuncSetAttribute(hgemm_out, cudaFuncAttributeMaxDynamicSharedMemorySize, 2 * HG_ST);
    cudaFuncSetAttribute(scores_mma, cudaFuncAttributeMaxDynamicSharedMemorySize, SC_SMEM);
    cudaFuncSetAttribute(ctx_mma, cudaFuncAttributeMaxDynamicSharedMemorySize, 55296);

    const int n4 = M_ * D_ / 4;
    split3_kernel<<<dim3(n4 / 256, 3), 256>>>(
        (const float4*)hidden, (const float4*)key, (const float4*)ctxv,
        (bf4*)hidHi, (bf4*)hidLo, (bf4*)keyHi, (bf4*)keyLo, (bf4*)cvHi, (bf4*)cvLo, n4);
    tsplit4_kernel<<<dim3(32, 32, 4), dim3(32, 8)>>>(
        Wq, Wk, Wv, Wo, WqHi, WqLo, WkHi, WkLo, WvHi, WvLo, WoHi, WoLo);

    hgemm_qkv<<<dim3(8, 64, 3), 256, 2 * HG_ST>>>(
        hidHi, hidLo, keyHi, keyLo, cvHi, cvLo,
        WqHi, WqLo, WkHi, WkLo, WvHi, WvLo,
        bq, bk, bv, qHi, qLo, kHi, kLo, vHi, vLo);

    scores_mma<<<dim3(32, 128), 256, SC_SMEM>>>(qHi, qLo, kHi, kLo, attnp, pHi, pLo);

    ctx_mma<<<dim3(8, 128), 256, 55296>>>(pHi, pLo, vHi, vLo, ctxHi, ctxLo);

    hgemm_out<<<dim3(8, 64), 256, 2 * HG_ST>>>(ctxHi, ctxLo, WoHi, WoLo, bo, outp);
}

// round 13
// speedup vs baseline: 1.0017x; 1.0017x over previous
#include <cuda_runtime.h>
#include <cuda_bf16.h>
#include <cstdint>

#define B_  8
#define L_  1024
#define D_  1024
#define H_  16
#define DK_ 64
#define M_  (B_*L_)   // 8192

// ---------------- scratch (device globals) ----------------
__device__ __nv_bfloat16 g_qHi[M_*D_], g_qLo[M_*D_];   // [B,H,L,64]
__device__ __nv_bfloat16 g_kHi[M_*D_], g_kLo[M_*D_];
__device__ __nv_bfloat16 g_vHi[M_*D_], g_vLo[M_*D_];
__device__ __nv_bfloat16 g_pHi[134217728], g_pLo[134217728];   // P (attn) bf16 hi/lo
__device__ float g_outs[M_*D_];
__device__ __nv_bfloat16 g_hidHi[M_*D_], g_hidLo[M_*D_];
__device__ __nv_bfloat16 g_keyHi[M_*D_], g_keyLo[M_*D_];
__device__ __nv_bfloat16 g_cvHi [M_*D_], g_cvLo [M_*D_];
__device__ __nv_bfloat16 g_ctxHi[M_*D_], g_ctxLo[M_*D_];
__device__ __nv_bfloat16 g_WqHi[D_*D_], g_WqLo[D_*D_];
__device__ __nv_bfloat16 g_WkHi[D_*D_], g_WkLo[D_*D_];
__device__ __nv_bfloat16 g_WvHi[D_*D_], g_WvLo[D_*D_];
__device__ __nv_bfloat16 g_WoHi[D_*D_], g_WoLo[D_*D_];

// ---------------- helpers ----------------
__device__ __forceinline__ uint32_t smem_u32(const void* p) {
    return (uint32_t)__cvta_generic_to_shared((void*)p);
}
#define CP_COMMIT() asm volatile("cp.async.commit_group;" ::: "memory")
#define CP_WAIT0()  asm volatile("cp.async.wait_group 0;" ::: "memory")
#define CP_WAIT1()  asm volatile("cp.async.wait_group 1;" ::: "memory")
__device__ __forceinline__ void cp16(uint32_t dst, const void* src) {
    asm volatile("cp.async.cg.shared.global [%0], [%1], 16;" :: "r"(dst), "l"(src));
}
__device__ __forceinline__ void ldsm4(uint32_t* r, uint32_t a) {
    asm volatile("ldmatrix.sync.aligned.m8n8.x4.shared.b16 {%0,%1,%2,%3}, [%4];"
        : "=r"(r[0]), "=r"(r[1]), "=r"(r[2]), "=r"(r[3]) : "r"(a));
}
__device__ __forceinline__ void ldsm4t(uint32_t* r, uint32_t a) {
    asm volatile("ldmatrix.sync.aligned.m8n8.x4.trans.shared.b16 {%0,%1,%2,%3}, [%4];"
        : "=r"(r[0]), "=r"(r[1]), "=r"(r[2]), "=r"(r[3]) : "r"(a));
}
__device__ __forceinline__ void mma_bf16(float* c, const uint32_t* a, const uint32_t* b) {
    asm volatile("mma.sync.aligned.m16n8k16.row.col.f32.bf16.bf16.f32 "
        "{%0,%1,%2,%3}, {%4,%5,%6,%7}, {%8,%9}, {%0,%1,%2,%3};"
        : "+f"(c[0]), "+f"(c[1]), "+f"(c[2]), "+f"(c[3])
        : "r"(a[0]), "r"(a[1]), "r"(a[2]), "r"(a[3]), "r"(b[0]), "r"(b[1]));
}
__device__ __forceinline__ void hilo_pack(float a, float b, uint32_t& hi, uint32_t& lo) {
    __nv_bfloat16 ha = __float2bfloat16(a), hb = __float2bfloat16(b);
    __nv_bfloat16 la = __float2bfloat16(a - __bfloat162float(ha));
    __nv_bfloat16 lb = __float2bfloat16(b - __bfloat162float(hb));
    hi = (uint32_t)__bfloat16_as_ushort(ha) | ((uint32_t)__bfloat16_as_ushort(hb) << 16);
    lo = (uint32_t)__bfloat16_as_ushort(la) | ((uint32_t)__bfloat16_as_ushort(lb) << 16);
}

// ---------------- prep: fp32 -> bf16 hi/lo (batched) ----------------
struct __align__(8) bf4 { __nv_bfloat16 x, y, z, w; };
__global__ void split3_kernel(const float4* __restrict__ X0, const float4* __restrict__ X1,
                              const float4* __restrict__ X2,
                              bf4* __restrict__ H0, bf4* __restrict__ L0,
                              bf4* __restrict__ H1, bf4* __restrict__ L1,
                              bf4* __restrict__ H2, bf4* __restrict__ L2, int n4)
{
    const float4* X; bf4 *Hi, *Lo;
    if (blockIdx.y == 0)      { X = X0; Hi = H0; Lo = L0; }
    else if (blockIdx.y == 1) { X = X1; Hi = H1; Lo = L1; }
    else                      { X = X2; Hi = H2; Lo = L2; }
    int i = blockIdx.x * 256 + threadIdx.x;
    if (i >= n4) return;
    float4 v = X[i];
    bf4 h, l;
    h.x = __float2bfloat16(v.x); l.x = __float2bfloat16(v.x - __bfloat162float(h.x));
    h.y = __float2bfloat16(v.y); l.y = __float2bfloat16(v.y - __bfloat162float(h.y));
    h.z = __float2bfloat16(v.z); l.z = __float2bfloat16(v.z - __bfloat162float(h.z));
    h.w = __float2bfloat16(v.w); l.w = __float2bfloat16(v.w - __bfloat162float(h.w));
    Hi[i] = h; Lo[i] = l;
}
__global__ void tsplit4_kernel(const float* __restrict__ W0, const float* __restrict__ W1,
                               const float* __restrict__ W2, const float* __restrict__ W3,
                               __nv_bfloat16* __restrict__ H0, __nv_bfloat16* __restrict__ L0,
                               __nv_bfloat16* __restrict__ H1, __nv_bfloat16* __restrict__ L1,
                               __nv_bfloat16* __restrict__ H2, __nv_bfloat16* __restrict__ L2,
                               __nv_bfloat16* __restrict__ H3, __nv_bfloat16* __restrict__ L3)
{
    const float* W; __nv_bfloat16 *Hi, *Lo;
    int z = blockIdx.z;
    if (z == 0)      { W = W0; Hi = H0; Lo = L0; }
    else if (z == 1) { W = W1; Hi = H1; Lo = L1; }
    else if (z == 2) { W = W2; Hi = H2; Lo = L2; }
    else             { W = W3; Hi = H3; Lo = L3; }
    __shared__ float t[32][33];
    int bx = blockIdx.x * 32, by = blockIdx.y * 32;
    int x = threadIdx.x, y = threadIdx.y;
#pragma unroll
    for (int i = 0; i < 32; i += 8)
        t[y + i][x] = W[(size_t)(by + y + i) * D_ + bx + x];
    __syncthreads();
#pragma unroll
    for (int i = 0; i < 32; i += 8) {
        float v = t[x][y + i];
        __nv_bfloat16 h = __float2bfloat16(v);
        __nv_bfloat16 l = __float2bfloat16(v - __bfloat162float(h));
        size_t o = (size_t)(bx + y + i) * D_ + by + x;
        Hi[o] = h; Lo[o] = l;
    }
}

// ---------------- HMMA GEMM (R3 config): 128x128 tile, 256 threads ----------------
#define HG_ST 40960u
template <int MODE>
__device__ __forceinline__
void hgemm_body(const __nv_bfloat16* __restrict__ AHi, const __nv_bfloat16* __restrict__ ALo,
                const __nv_bfloat16* __restrict__ BHi, const __nv_bfloat16* __restrict__ BLo,
                const float* __restrict__ bias,
                float* __restrict__ C, __nv_bfloat16* __restrict__ CHi, __nv_bfloat16* __restrict__ CLo,
                char* smc)
{
    const int tid = threadIdx.x, lane = tid & 31, wid = tid >> 5;
    const int wm = wid >> 2, wn = wid & 3;
    const int n0 = blockIdx.x * 128, m0 = blockIdx.y * 128;
    const uint32_t sb = smem_u32(smc);

    const int lr = tid >> 2, lc = tid & 3;
    const int arow = wm * 64 + (lane & 15);
    const uint32_t akb = (lane >> 4) * 16;
    const int bn8 = (lane & 16) ? 8 : 0;
    const uint32_t bkh = (lane & 8) ? 16 : 0;
    const int br = lane & 7;

    float acc[4][4][4];
#pragma unroll
    for (int i = 0; i < 4; i++)
#pragma unroll
        for (int j = 0; j < 4; j++)
#pragma unroll
            for (int q = 0; q < 4; q++) acc[i][j][q] = 0.f;

    auto load_stage = [&](int s, int buf) {
        uint32_t base = sb + buf * HG_ST;
        int k0 = s * 32;
#pragma unroll
        for (int half = 0; half < 2; half++) {
            int row = lr + half * 64;
            uint32_t doff = row * 80 + lc * 16;
            cp16(base + doff,          AHi + (size_t)(m0 + row) * D_ + k0 + lc * 8);
            cp16(base + 10240 + doff,  ALo + (size_t)(m0 + row) * D_ + k0 + lc * 8);
            cp16(base + 20480 + doff,  BHi + (size_t)(n0 + row) * D_ + k0 + lc * 8);
            cp16(base + 30720 + doff,  BLo + (size_t)(n0 + row) * D_ + k0 + lc * 8);
        }
    };

    load_stage(0, 0); CP_COMMIT();

    for (int s = 0; s < 32; s++) {
        if (s < 31) { load_stage(s + 1, (s + 1) & 1); CP_COMMIT(); CP_WAIT1(); }
        else        { CP_WAIT0(); }
        __syncthreads();
        uint32_t aHiB = sb + (s & 1) * HG_ST;
        uint32_t aLoB = aHiB + 10240, bHiB = aHiB + 20480, bLoB = aHiB + 30720;
#pragma unroll
        for (int h = 0; h < 2; h++) {
            uint32_t bhi[2][4], blo[2][4];
#pragma unroll
            for (int g = 0; g < 2; g++) {
                uint32_t ba = (uint32_t)(wn * 32 + g * 16 + bn8 + br) * 80 + h * 32 + bkh;
                ldsm4(bhi[g], bHiB + ba);
                ldsm4(blo[g], bLoB + ba);
            }
#pragma unroll
            for (int mf = 0; mf < 4; mf++) {
                uint32_t ah[4], al[4];
                uint32_t aa = (uint32_t)(arow + mf * 16) * 80 + h * 32 + akb;
                ldsm4(ah, aHiB + aa);
                ldsm4(al, aLoB + aa);
#pragma unroll
                for (int g = 0; g < 2; g++)
#pragma unroll
                    for (int j = 0; j < 2; j++) {
                        float* c = acc[mf][g * 2 + j];
                        mma_bf16(c, ah, &bhi[g][j * 2]);
                        mma_bf16(c, ah, &blo[g][j * 2]);
                        mma_bf16(c, al, &bhi[g][j * 2]);
                    }
            }
        }
        __syncthreads();
    }

#pragma unroll
    for (int mf = 0; mf < 4; mf++)
#pragma unroll
        for (int nf = 0; nf < 4; nf++) {
            int col = n0 + wn * 32 + nf * 8 + (lane & 3) * 2;
            float b0 = __ldg(bias + col), b1 = __ldg(bias + col + 1);
            int r0 = m0 + wm * 64 + mf * 16 + (lane >> 2);
#pragma unroll
            for (int half = 0; half < 2; half++) {
                int r = r0 + half * 8;
                float v0 = acc[mf][nf][half * 2 + 0] + b0;
                float v1 = acc[mf][nf][half * 2 + 1] + b1;
                if (MODE == 0) {
                    *(float2*)(C + (size_t)r * D_ + col) = make_float2(v0, v1);
                } else {
                    int hh = col >> 6, d = col & 63;
                    int bb = r >> 10, l = r & 1023;
                    size_t dst = (((size_t)(bb * H_ + hh) * L_ + l) * DK_) + d;
                    uint32_t hi, lo;
                    hilo_pack(v0, v1, hi, lo);
                    *(uint32_t*)(CHi + dst) = hi;
                    *(uint32_t*)(CLo + dst) = lo;
                }
            }
        }
}

__global__ __launch_bounds__(256)
void hgemm_qkv(const __nv_bfloat16* hidHi, const __nv_bfloat16* hidLo,
               const __nv_bfloat16* keyHi, const __nv_bfloat16* keyLo,
               const __nv_bfloat16* cvHi,  const __nv_bfloat16* cvLo,
               const __nv_bfloat16* WqHi, const __nv_bfloat16* WqLo,
               const __nv_bfloat16* WkHi, const __nv_bfloat16* WkLo,
               const __nv_bfloat16* WvHi, const __nv_bfloat16* WvLo,
               const float* bq, const float* bk, const float* bv,
               __nv_bfloat16* qHi, __nv_bfloat16* qLo,
               __nv_bfloat16* kHi, __nv_bfloat16* kLo,
               __nv_bfloat16* vHi, __nv_bfloat16* vLo)
{
    extern __shared__ char smc[];
    const __nv_bfloat16 *AHi, *ALo, *BHi, *BLo;
    const float* bias;
    __nv_bfloat16 *CHi, *CLo;
    int z = blockIdx.z;
    if (z == 0)      { AHi = hidHi; ALo = hidLo; BHi = WqHi; BLo = WqLo; bias = bq; CHi = qHi; CLo = qLo; }
    else if (z == 1) { AHi = keyHi; ALo = keyLo; BHi = WkHi; BLo = WkLo; bias = bk; CHi = kHi; CLo = kLo; }
    else             { AHi = cvHi;  ALo = cvLo;  BHi = WvHi; BLo = WvLo; bias = bv; CHi = vHi; CLo = vLo; }
    hgemm_body<1>(AHi, ALo, BHi, BLo, bias, nullptr, CHi, CLo, smc);
}

__global__ __launch_bounds__(256)
void hgemm_out(const __nv_bfloat16* AHi, const __nv_bfloat16* ALo,
               const __nv_bfloat16* BHi, const __nv_bfloat16* BLo,
               const float* bias, float* C)
{
    extern __shared__ char smc[];
    hgemm_body<0>(AHi, ALo, BHi, BLo, bias, C, nullptr, nullptr, smc);
}

// ---------------- scores (Q hoisted) + softmax + bf16 hi/lo P emit ----------------
#define SC_SMEM 215168u
__global__ __launch_bounds__(256)
void scores_mma(const __nv_bfloat16* __restrict__ QHi, const __nv_bfloat16* __restrict__ QLo,
                const __nv_bfloat16* __restrict__ KHi, const __nv_bfloat16* __restrict__ KLo,
                float* __restrict__ attn,
                __nv_bfloat16* __restrict__ PHi, __nv_bfloat16* __restrict__ PLo)
{
    extern __shared__ char smc[];
    const int tid = threadIdx.x, lane = tid & 31, wid = tid >> 5;
    const int wm = wid >> 2, wn = wid & 3;
    const int bh = blockIdx.y, q0 = blockIdx.x * 32;
    const uint32_t sb = smem_u32(smc);
    float* Ss = (float*)(smc + 82944);
    float* sinv = (float*)(smc + 215040);

    {
        int row = tid >> 3, ch = tid & 7;
        const size_t src = ((size_t)bh * L_ + q0 + row) * DK_ + ch * 8;
        cp16(sb + row * 144 + ch * 16, QHi + src);
        cp16(sb + 4608 + row * 144 + ch * 16, QLo + src);
    }
    auto loadK = [&](int cc, int buf) {
        uint32_t base = sb + 9216 + buf * 36864;
#pragma unroll
        for (int i = 0; i < 4; i++) {
            int idx = tid + i * 256;
            int row = idx >> 3, ch = idx & 7;
            const size_t src = ((size_t)bh * L_ + cc * 128 + row) * DK_ + ch * 8;
            cp16(base + row * 144 + ch * 16, KHi + src);
            cp16(base + 18432 + row * 144 + ch * 16, KLo + src);
        }
    };
    loadK(0, 0); CP_COMMIT();
    CP_WAIT0();
    __syncthreads();     // Q + K0 resident

    const uint32_t akb = (lane >> 4) * 16;
    const int bn8 = (lane & 16) ? 8 : 0;
    const uint32_t bkh = (lane & 8) ? 16 : 0;
    const int br = lane & 7;

    // hoist Q fragments (static across all K chunks)
    uint32_t qh[4][4], ql[4][4];
#pragma unroll
    for (int h = 0; h < 4; h++) {
        uint32_t aa = (uint32_t)(wm * 16 + (lane & 15)) * 144 + h * 32 + akb;
        ldsm4(qh[h], sb + aa);
        ldsm4(ql[h], sb + 4608 + aa);
    }

    for (int cc = 0; cc < 8; cc++) {
        if (cc < 7) { loadK(cc + 1, (cc + 1) & 1); CP_COMMIT(); CP_WAIT1(); }
        else        { CP_WAIT0(); }
        __syncthreads();
        uint32_t kHiB = sb + 9216 + (cc & 1) * 36864;
        uint32_t kLoB = kHiB + 18432;
        float acc[4][4];
#pragma unroll
        for (int i = 0; i < 4; i++)
#pragma unroll
            for (int q = 0; q < 4; q++) acc[i][q] = 0.f;
#pragma unroll
        for (int h = 0; h < 4; h++) {
            uint32_t bhi[2][4], blo[2][4];
#pragma unroll
            for (int g = 0; g < 2; g++) {
                uint32_t ba = (uint32_t)(wn * 32 + g * 16 + bn8 + br) * 144 + h * 32 + bkh;
                ldsm4(bhi[g], kHiB + ba);
                ldsm4(blo[g], kLoB + ba);
            }
#pragma unroll
            for (int g = 0; g < 2; g++)
#pragma unroll
                for (int j = 0; j < 2; j++) {
                    float* c = acc[g * 2 + j];
                    mma_bf16(c, qh[h], &bhi[g][j * 2]);
                    mma_bf16(c, qh[h], &blo[g][j * 2]);
                    mma_bf16(c, ql[h], &bhi[g][j * 2]);
                }
        }
#pragma unroll
        for (int nf = 0; nf < 4; nf++) {
            int col = cc * 128 + wn * 32 + nf * 8 + (lane & 3) * 2;
            int row = wm * 16 + (lane >> 2);
            *(float2*)(Ss + (size_t)row * 1032 + col) =
                make_float2(acc[nf][0] * 0.125f, acc[nf][1] * 0.125f);
            *(float2*)(Ss + (size_t)(row + 8) * 1032 + col) =
                make_float2(acc[nf][2] * 0.125f, acc[nf][3] * 0.125f);
        }
        __syncthreads();
    }

    int r = tid >> 3, g = tid & 7;
    float m = -1e30f;
    for (int c = g; c < 1024; c += 8) m = fmaxf(m, Ss[r * 1032 + c]);
#pragma unroll
    for (int o = 4; o; o >>= 1) m = fmaxf(m, __shfl_xor_sync(0xffffffffu, m, o));
    float s = 0.f;
    for (int c = g; c < 1024; c += 8) {
        float e = __expf(Ss[r * 1032 + c] - m);
        s += e;
        Ss[r * 1032 + c] = e;
    }
#pragma unroll
    for (int o = 4; o; o >>= 1) s += __shfl_xor_sync(0xffffffffu, s, o);
    if (g == 0) sinv[r] = 1.f / s;
    __syncthreads();

    // epilogue: normalized P -> fp32 attn (optional) + bf16 hi/lo P (always)
    float* Ap = attn ? attn + ((size_t)bh * L_ + q0) * L_ : nullptr;
    __nv_bfloat16* PhP = PHi + ((size_t)bh * L_ + q0) * L_;
    __nv_bfloat16* PlP = PLo + ((size_t)bh * L_ + q0) * L_;
    for (int idx = tid; idx < 32 * 1024 / 4; idx += 256) {
        int rr = idx >> 8, c4 = idx & 255;
        float inv = sinv[rr];
        float4 v;
        v.x = Ss[rr * 1032 + c4 * 4 + 0] * inv;
        v.y = Ss[rr * 1032 + c4 * 4 + 1] * inv;
        v.z = Ss[rr * 1032 + c4 * 4 + 2] * inv;
        v.w = Ss[rr * 1032 + c4 * 4 + 3] * inv;
        if (Ap) ((float4*)Ap)[idx] = v;
        uint32_t h0, l0, h1, l1;
        hilo_pack(v.x, v.y, h0, l0);
        hilo_pack(v.z, v.w, h1, l1);
        ((uint2*)PhP)[idx] = make_uint2(h0, h1);
        ((uint2*)PlP)[idx] = make_uint2(l0, l1);
    }
}

// ---------------- ctx = P @ V (HMMA): P bf16 hi/lo via cp.async, no conversion ----------------
// smem: Phi 0 (128*144) | Plo 18432 | Vhi 36864 (64*144) | Vlo 46080 ; total 55296
__global__ __launch_bounds__(256)
void ctx_mma(const __nv_bfloat16* __restrict__ PHi, const __nv_bfloat16* __restrict__ PLo,
             const __nv_bfloat16* __restrict__ VHi, const __nv_bfloat16* __restrict__ VLo,
             __nv_bfloat16* __restrict__ CHi, __nv_bfloat16* __restrict__ CLo)
{
    extern __shared__ char smc[];
    const int tid = threadIdx.x, lane = tid & 31, wid = tid >> 5;
    const int wm = wid >> 1, wn = wid & 1;
    const int bh = blockIdx.y, q0 = blockIdx.x * 128;
    const int b = bh >> 4, hh = bh & 15;
    const uint32_t sb = smem_u32(smc);

    float acc[2][4][4];
#pragma unroll
    for (int i = 0; i < 2; i++)
#pragma unroll
        for (int j = 0; j < 4; j++)
#pragma unroll
            for (int q = 0; q < 4; q++) acc[i][j][q] = 0.f;

    const uint32_t akb = (lane >> 4) * 16;
    const int vkoff = ((lane & 8) ? 8 : 0) + (lane & 7);
    const int vdoff = (lane & 16) ? 8 : 0;

    for (int k0 = 0; k0 < L_; k0 += 64) {
        // V chunk: 64 rows x 64 cols bf16 (hi+lo)
#pragma unroll
        for (int i = 0; i < 2; i++) {
            int idx = tid + i * 256;
            int row = idx >> 3, ch = idx & 7;
            const size_t src = ((size_t)bh * L_ + k0 + row) * DK_ + ch * 8;
            cp16(sb + 36864 + row * 144 + ch * 16, VHi + src);
            cp16(sb + 46080 + row * 144 + ch * 16, VLo + src);
        }
        // P chunk: 128 q-rows x 64 k bf16 (hi+lo) straight from gmem
#pragma unroll
        for (int i = 0; i < 4; i++) {
            int idx = tid + i * 256;
            int row = idx >> 3, ch = idx & 7;
            const size_t src = ((size_t)bh * L_ + q0 + row) * L_ + k0 + ch * 8;
            cp16(sb + row * 144 + ch * 16, PHi + src);
            cp16(sb + 18432 + row * 144 + ch * 16, PLo + src);
        }
        CP_COMMIT();
        CP_WAIT0();
        __syncthreads();
#pragma unroll
        for (int h = 0; h < 4; h++) {
            uint32_t vhi[2][4], vlo[2][4];
#pragma unroll
            for (int g = 0; g < 2; g++) {
                uint32_t va = (uint32_t)(h * 16 + vkoff) * 144
                            + (uint32_t)(wn * 32 + g * 16 + vdoff) * 2;
                ldsm4t(vhi[g], sb + 36864 + va);
                ldsm4t(vlo[g], sb + 46080 + va);
            }
#pragma unroll
            for (int mf = 0; mf < 2; mf++) {
                uint32_t ah[4], al[4];
                uint32_t aa = (uint32_t)(wm * 32 + mf * 16 + (lane & 15)) * 144 + h * 32 + akb;
                ldsm4(ah, sb + aa);
                ldsm4(al, sb + 18432 + aa);
#pragma unroll
                for (int g = 0; g < 2; g++)
#pragma unroll
                    for (int j = 0; j < 2; j++) {
                        float* c = acc[mf][g * 2 + j];
                        mma_bf16(c, ah, &vhi[g][j * 2]);
                        mma_bf16(c, ah, &vlo[g][j * 2]);
                        mma_bf16(c, al, &vhi[g][j * 2]);
                    }
            }
        }
        __syncthreads();
    }

#pragma unroll
    for (int mf = 0; mf < 2; mf++)
#pragma unroll
        for (int nf = 0; nf < 4; nf++) {
            int d = wn * 32 + nf * 8 + (lane & 3) * 2;
            int q = q0 + wm * 32 + mf * 16 + (lane >> 2);
#pragma unroll
            for (int half = 0; half < 2; half++) {
                int qq = q + half * 8;
                size_t dst = ((size_t)(b * L_ + qq)) * D_ + hh * DK_ + d;
                uint32_t hi, lo;
                hilo_pack(acc[mf][nf][half * 2 + 0], acc[mf][nf][half * 2 + 1], hi, lo);
                *(uint32_t*)(CHi + dst) = hi;
                *(uint32_t*)(CLo + dst) = lo;
            }
        }
}

// ---------------------------------------------------------------------------
extern "C" void kernel_launch(void* const* d_in, const int* in_sizes, int n_in,
                              void* d_out, int out_size)
{
    const float* hidden = (const float*)d_in[0];
    const float* key    = (const float*)d_in[1];
    const float* ctxv   = (const float*)d_in[2];
    const float* Wq = (const float*)d_in[3];
    const float* bq = (const float*)d_in[4];
    const float* Wk = (const float*)d_in[5];
    const float* bk = (const float*)d_in[6];
    const float* Wv = (const float*)d_in[7];
    const float* bv = (const float*)d_in[8];
    const float* Wo = (const float*)d_in[9];
    const float* bo = (const float*)d_in[10];

    float *op;
    cudaGetSymbolAddress((void**)&op, g_outs);
    __nv_bfloat16 *qHi,*qLo,*kHi,*kLo,*vHi,*vLo,*pHi,*pLo;
    cudaGetSymbolAddress((void**)&qHi, g_qHi); cudaGetSymbolAddress((void**)&qLo, g_qLo);
    cudaGetSymbolAddress((void**)&kHi, g_kHi); cudaGetSymbolAddress((void**)&kLo, g_kLo);
    cudaGetSymbolAddress((void**)&vHi, g_vHi); cudaGetSymbolAddress((void**)&vLo, g_vLo);
    cudaGetSymbolAddress((void**)&pHi, g_pHi); cudaGetSymbolAddress((void**)&pLo, g_pLo);
    __nv_bfloat16 *hidHi,*hidLo,*keyHi,*keyLo,*cvHi,*cvLo,*ctxHi,*ctxLo;
    cudaGetSymbolAddress((void**)&hidHi, g_hidHi); cudaGetSymbolAddress((void**)&hidLo, g_hidLo);
    cudaGetSymbolAddress((void**)&keyHi, g_keyHi); cudaGetSymbolAddress((void**)&keyLo, g_keyLo);
    cudaGetSymbolAddress((void**)&cvHi,  g_cvHi);  cudaGetSymbolAddress((void**)&cvLo,  g_cvLo);
    cudaGetSymbolAddress((void**)&ctxHi, g_ctxHi); cudaGetSymbolAddress((void**)&ctxLo, g_ctxLo);
    __nv_bfloat16 *WqHi,*WqLo,*WkHi,*WkLo,*WvHi,*WvLo,*WoHi,*WoLo;
    cudaGetSymbolAddress((void**)&WqHi, g_WqHi); cudaGetSymbolAddress((void**)&WqLo, g_WqLo);
    cudaGetSymbolAddress((void**)&WkHi, g_WkHi); cudaGetSymbolAddress((void**)&WkLo, g_WkLo);
    cudaGetSymbolAddress((void**)&WvHi, g_WvHi); cudaGetSymbolAddress((void**)&WvLo, g_WvLo);
    cudaGetSymbolAddress((void**)&WoHi, g_WoHi); cudaGetSymbolAddress((void**)&WoLo, g_WoLo);

    const size_t out_elems  = (size_t)B_ * L_ * D_;
    const size_t attn_elems = (size_t)B_ * H_ * L_ * L_;
    float* outp;
    float* attnp;   // nullptr -> fp32 attn not needed
    if ((size_t)out_size >= out_elems + attn_elems) {
        outp  = (float*)d_out;
        attnp = (float*)d_out + out_elems;
    } else if ((size_t)out_size == attn_elems) {
        outp  = op;
        attnp = (float*)d_out;
    } else {
        outp  = (float*)d_out;
        attnp = nullptr;          // attn not checked; skip fp32 write
    }

    cudaFuncSetAttribute(hgemm_qkv, cudaFuncAttributeMaxDynamicSharedMemorySize, 2 * HG_ST);
    cudaFuncSetAttribute(hgemm_out, cudaFuncAttributeMaxDynamicSharedMemorySize, 2 * HG_ST);
    cudaFuncSetAttribute(scores_mma, cudaFuncAttributeMaxDynamicSharedMemorySize, SC_SMEM);
    cudaFuncSetAttribute(ctx_mma, cudaFuncAttributeMaxDynamicSharedMemorySize, 55296);

    const int n4 = M_ * D_ / 4;
    split3_kernel<<<dim3(n4 / 256, 3), 256>>>(
        (const float4*)hidden, (const float4*)key, (const float4*)ctxv,
        (bf4*)hidHi, (bf4*)hidLo, (bf4*)keyHi, (bf4*)keyLo, (bf4*)cvHi, (bf4*)cvLo, n4);
    tsplit4_kernel<<<dim3(32, 32, 4), dim3(32, 8)>>>(
        Wq, Wk, Wv, Wo, WqHi, WqLo, WkHi, WkLo, WvHi, WvLo, WoHi, WoLo);

    hgemm_qkv<<<dim3(8, 64, 3), 256, 2 * HG_ST>>>(
        hidHi, hidLo, keyHi, keyLo, cvHi, cvLo,
        WqHi, WqLo, WkHi, WkLo, WvHi, WvLo,
        bq, bk, bv, qHi, qLo, kHi, kLo, vHi, vLo);

    scores_mma<<<dim3(32, 128), 256, SC_SMEM>>>(qHi, qLo, kHi, kLo, attnp, pHi, pLo);

    ctx_mma<<<dim3(8, 128), 256, 55296>>>(pHi, pLo, vHi, vLo, ctxHi, ctxLo);

    hgemm_out<<<dim3(8, 64), 256, 2 * HG_ST>>>(ctxHi, ctxLo, WoHi, WoLo, bo, outp);
}

// round 14
// speedup vs baseline: 1.0020x; 1.0003x over previous
#include <cuda_runtime.h>
#include <cuda_bf16.h>
#include <cstdint>

#define B_  8
#define L_  1024
#define D_  1024
#define H_  16
#define DK_ 64
#define M_  (B_*L_)   // 8192

// ---------------- scratch (device globals) ----------------
__device__ __nv_bfloat16 g_qHi[M_*D_], g_qLo[M_*D_];   // [B,H,L,64]
__device__ __nv_bfloat16 g_kHi[M_*D_], g_kLo[M_*D_];
__device__ __nv_bfloat16 g_vHi[M_*D_], g_vLo[M_*D_];
__device__ __nv_bfloat16 g_pHi[134217728], g_pLo[134217728];   // P (attn) bf16 hi/lo
__device__ float g_outs[M_*D_];
__device__ __nv_bfloat16 g_hidHi[M_*D_], g_hidLo[M_*D_];
__device__ __nv_bfloat16 g_keyHi[M_*D_], g_keyLo[M_*D_];
__device__ __nv_bfloat16 g_cvHi [M_*D_], g_cvLo [M_*D_];
__device__ __nv_bfloat16 g_ctxHi[M_*D_], g_ctxLo[M_*D_];
__device__ __nv_bfloat16 g_WqHi[D_*D_], g_WqLo[D_*D_];
__device__ __nv_bfloat16 g_WkHi[D_*D_], g_WkLo[D_*D_];
__device__ __nv_bfloat16 g_WvHi[D_*D_], g_WvLo[D_*D_];
__device__ __nv_bfloat16 g_WoHi[D_*D_], g_WoLo[D_*D_];

// ---------------- helpers ----------------
__device__ __forceinline__ uint32_t smem_u32(const void* p) {
    return (uint32_t)__cvta_generic_to_shared((void*)p);
}
#define CP_COMMIT() asm volatile("cp.async.commit_group;" ::: "memory")
#define CP_WAIT0()  asm volatile("cp.async.wait_group 0;" ::: "memory")
#define CP_WAIT1()  asm volatile("cp.async.wait_group 1;" ::: "memory")
__device__ __forceinline__ void cp16(uint32_t dst, const void* src) {
    asm volatile("cp.async.cg.shared.global [%0], [%1], 16;" :: "r"(dst), "l"(src));
}
__device__ __forceinline__ void ldsm4(uint32_t* r, uint32_t a) {
    asm volatile("ldmatrix.sync.aligned.m8n8.x4.shared.b16 {%0,%1,%2,%3}, [%4];"
        : "=r"(r[0]), "=r"(r[1]), "=r"(r[2]), "=r"(r[3]) : "r"(a));
}
__device__ __forceinline__ void ldsm4t(uint32_t* r, uint32_t a) {
    asm volatile("ldmatrix.sync.aligned.m8n8.x4.trans.shared.b16 {%0,%1,%2,%3}, [%4];"
        : "=r"(r[0]), "=r"(r[1]), "=r"(r[2]), "=r"(r[3]) : "r"(a));
}
__device__ __forceinline__ void mma_bf16(float* c, const uint32_t* a, const uint32_t* b) {
    asm volatile("mma.sync.aligned.m16n8k16.row.col.f32.bf16.bf16.f32 "
        "{%0,%1,%2,%3}, {%4,%5,%6,%7}, {%8,%9}, {%0,%1,%2,%3};"
        : "+f"(c[0]), "+f"(c[1]), "+f"(c[2]), "+f"(c[3])
        : "r"(a[0]), "r"(a[1]), "r"(a[2]), "r"(a[3]), "r"(b[0]), "r"(b[1]));
}
__device__ __forceinline__ void hilo_pack(float a, float b, uint32_t& hi, uint32_t& lo) {
    __nv_bfloat16 ha = __float2bfloat16(a), hb = __float2bfloat16(b);
    __nv_bfloat16 la = __float2bfloat16(a - __bfloat162float(ha));
    __nv_bfloat16 lb = __float2bfloat16(b - __bfloat162float(hb));
    hi = (uint32_t)__bfloat16_as_ushort(ha) | ((uint32_t)__bfloat16_as_ushort(hb) << 16);
    lo = (uint32_t)__bfloat16_as_ushort(la) | ((uint32_t)__bfloat16_as_ushort(lb) << 16);
}

// ---------------- prep: fp32 -> bf16 hi/lo (batched) ----------------
struct __align__(8) bf4 { __nv_bfloat16 x, y, z, w; };
__global__ void split3_kernel(const float4* __restrict__ X0, const float4* __restrict__ X1,
                              const float4* __restrict__ X2,
                              bf4* __restrict__ H0, bf4* __restrict__ L0,
                              bf4* __restrict__ H1, bf4* __restrict__ L1,
                              bf4* __restrict__ H2, bf4* __restrict__ L2, int n4)
{
    const float4* X; bf4 *Hi, *Lo;
    if (blockIdx.y == 0)      { X = X0; Hi = H0; Lo = L0; }
    else if (blockIdx.y == 1) { X = X1; Hi = H1; Lo = L1; }
    else                      { X = X2; Hi = H2; Lo = L2; }
    int i = blockIdx.x * 256 + threadIdx.x;
    if (i >= n4) return;
    float4 v = X[i];
    bf4 h, l;
    h.x = __float2bfloat16(v.x); l.x = __float2bfloat16(v.x - __bfloat162float(h.x));
    h.y = __float2bfloat16(v.y); l.y = __float2bfloat16(v.y - __bfloat162float(h.y));
    h.z = __float2bfloat16(v.z); l.z = __float2bfloat16(v.z - __bfloat162float(h.z));
    h.w = __float2bfloat16(v.w); l.w = __float2bfloat16(v.w - __bfloat162float(h.w));
    Hi[i] = h; Lo[i] = l;
}
__global__ void tsplit4_kernel(const float* __restrict__ W0, const float* __restrict__ W1,
                               const float* __restrict__ W2, const float* __restrict__ W3,
                               __nv_bfloat16* __restrict__ H0, __nv_bfloat16* __restrict__ L0,
                               __nv_bfloat16* __restrict__ H1, __nv_bfloat16* __restrict__ L1,
                               __nv_bfloat16* __restrict__ H2, __nv_bfloat16* __restrict__ L2,
                               __nv_bfloat16* __restrict__ H3, __nv_bfloat16* __restrict__ L3)
{
    const float* W; __nv_bfloat16 *Hi, *Lo;
    int z = blockIdx.z;
    if (z == 0)      { W = W0; Hi = H0; Lo = L0; }
    else if (z == 1) { W = W1; Hi = H1; Lo = L1; }
    else if (z == 2) { W = W2; Hi = H2; Lo = L2; }
    else             { W = W3; Hi = H3; Lo = L3; }
    __shared__ float t[32][33];
    int bx = blockIdx.x * 32, by = blockIdx.y * 32;
    int x = threadIdx.x, y = threadIdx.y;
#pragma unroll
    for (int i = 0; i < 32; i += 8)
        t[y + i][x] = W[(size_t)(by + y + i) * D_ + bx + x];
    __syncthreads();
#pragma unroll
    for (int i = 0; i < 32; i += 8) {
        float v = t[x][y + i];
        __nv_bfloat16 h = __float2bfloat16(v);
        __nv_bfloat16 l = __float2bfloat16(v - __bfloat162float(h));
        size_t o = (size_t)(bx + y + i) * D_ + by + x;
        Hi[o] = h; Lo[o] = l;
    }
}

// ---------------- HMMA GEMM (R3 config): 128x128 tile, 256 threads ----------------
#define HG_ST 40960u
template <int MODE>
__device__ __forceinline__
void hgemm_body(const __nv_bfloat16* __restrict__ AHi, const __nv_bfloat16* __restrict__ ALo,
                const __nv_bfloat16* __restrict__ BHi, const __nv_bfloat16* __restrict__ BLo,
                const float* __restrict__ bias,
                float* __restrict__ C, __nv_bfloat16* __restrict__ CHi, __nv_bfloat16* __restrict__ CLo,
                char* smc)
{
    const int tid = threadIdx.x, lane = tid & 31, wid = tid >> 5;
    const int wm = wid >> 2, wn = wid & 3;
    const int n0 = blockIdx.x * 128, m0 = blockIdx.y * 128;
    const uint32_t sb = smem_u32(smc);

    const int lr = tid >> 2, lc = tid & 3;
    const int arow = wm * 64 + (lane & 15);
    const uint32_t akb = (lane >> 4) * 16;
    const int bn8 = (lane & 16) ? 8 : 0;
    const uint32_t bkh = (lane & 8) ? 16 : 0;
    const int br = lane & 7;

    float acc[4][4][4];
#pragma unroll
    for (int i = 0; i < 4; i++)
#pragma unroll
        for (int j = 0; j < 4; j++)
#pragma unroll
            for (int q = 0; q < 4; q++) acc[i][j][q] = 0.f;

    auto load_stage = [&](int s, int buf) {
        uint32_t base = sb + buf * HG_ST;
        int k0 = s * 32;
#pragma unroll
        for (int half = 0; half < 2; half++) {
            int row = lr + half * 64;
            uint32_t doff = row * 80 + lc * 16;
            cp16(base + doff,          AHi + (size_t)(m0 + row) * D_ + k0 + lc * 8);
            cp16(base + 10240 + doff,  ALo + (size_t)(m0 + row) * D_ + k0 + lc * 8);
            cp16(base + 20480 + doff,  BHi + (size_t)(n0 + row) * D_ + k0 + lc * 8);
            cp16(base + 30720 + doff,  BLo + (size_t)(n0 + row) * D_ + k0 + lc * 8);
        }
    };

    load_stage(0, 0); CP_COMMIT();

    for (int s = 0; s < 32; s++) {
        if (s < 31) { load_stage(s + 1, (s + 1) & 1); CP_COMMIT(); CP_WAIT1(); }
        else        { CP_WAIT0(); }
        __syncthreads();
        uint32_t aHiB = sb + (s & 1) * HG_ST;
        uint32_t aLoB = aHiB + 10240, bHiB = aHiB + 20480, bLoB = aHiB + 30720;
#pragma unroll
        for (int h = 0; h < 2; h++) {
            uint32_t bhi[2][4], blo[2][4];
#pragma unroll
            for (int g = 0; g < 2; g++) {
                uint32_t ba = (uint32_t)(wn * 32 + g * 16 + bn8 + br) * 80 + h * 32 + bkh;
                ldsm4(bhi[g], bHiB + ba);
                ldsm4(blo[g], bLoB + ba);
            }
#pragma unroll
            for (int mf = 0; mf < 4; mf++) {
                uint32_t ah[4], al[4];
                uint32_t aa = (uint32_t)(arow + mf * 16) * 80 + h * 32 + akb;
                ldsm4(ah, aHiB + aa);
                ldsm4(al, aLoB + aa);
#pragma unroll
                for (int g = 0; g < 2; g++)
#pragma unroll
                    for (int j = 0; j < 2; j++) {
                        float* c = acc[mf][g * 2 + j];
                        mma_bf16(c, ah, &bhi[g][j * 2]);
                        mma_bf16(c, ah, &blo[g][j * 2]);
                        mma_bf16(c, al, &bhi[g][j * 2]);
                    }
            }
        }
        __syncthreads();
    }

#pragma unroll
    for (int mf = 0; mf < 4; mf++)
#pragma unroll
        for (int nf = 0; nf < 4; nf++) {
            int col = n0 + wn * 32 + nf * 8 + (lane & 3) * 2;
            float b0 = __ldg(bias + col), b1 = __ldg(bias + col + 1);
            int r0 = m0 + wm * 64 + mf * 16 + (lane >> 2);
#pragma unroll
            for (int half = 0; half < 2; half++) {
                int r = r0 + half * 8;
                float v0 = acc[mf][nf][half * 2 + 0] + b0;
                float v1 = acc[mf][nf][half * 2 + 1] + b1;
                if (MODE == 0) {
                    *(float2*)(C + (size_t)r * D_ + col) = make_float2(v0, v1);
                } else {
                    int hh = col >> 6, d = col & 63;
                    int bb = r >> 10, l = r & 1023;
                    size_t dst = (((size_t)(bb * H_ + hh) * L_ + l) * DK_) + d;
                    uint32_t hi, lo;
                    hilo_pack(v0, v1, hi, lo);
                    *(uint32_t*)(CHi + dst) = hi;
                    *(uint32_t*)(CLo + dst) = lo;
                }
            }
        }
}

__global__ __launch_bounds__(256)
void hgemm_qkv(const __nv_bfloat16* hidHi, const __nv_bfloat16* hidLo,
               const __nv_bfloat16* keyHi, const __nv_bfloat16* keyLo,
               const __nv_bfloat16* cvHi,  const __nv_bfloat16* cvLo,
               const __nv_bfloat16* WqHi, const __nv_bfloat16* WqLo,
               const __nv_bfloat16* WkHi, const __nv_bfloat16* WkLo,
               const __nv_bfloat16* WvHi, const __nv_bfloat16* WvLo,
               const float* bq, const float* bk, const float* bv,
               __nv_bfloat16* qHi, __nv_bfloat16* qLo,
               __nv_bfloat16* kHi, __nv_bfloat16* kLo,
               __nv_bfloat16* vHi, __nv_bfloat16* vLo)
{
    extern __shared__ char smc[];
    const __nv_bfloat16 *AHi, *ALo, *BHi, *BLo;
    const float* bias;
    __nv_bfloat16 *CHi, *CLo;
    int z = blockIdx.z;
    if (z == 0)      { AHi = hidHi; ALo = hidLo; BHi = WqHi; BLo = WqLo; bias = bq; CHi = qHi; CLo = qLo; }
    else if (z == 1) { AHi = keyHi; ALo = keyLo; BHi = WkHi; BLo = WkLo; bias = bk; CHi = kHi; CLo = kLo; }
    else             { AHi = cvHi;  ALo = cvLo;  BHi = WvHi; BLo = WvLo; bias = bv; CHi = vHi; CLo = vLo; }
    hgemm_body<1>(AHi, ALo, BHi, BLo, bias, nullptr, CHi, CLo, smc);
}

__global__ __launch_bounds__(256)
void hgemm_out(const __nv_bfloat16* AHi, const __nv_bfloat16* ALo,
               const __nv_bfloat16* BHi, const __nv_bfloat16* BLo,
               const float* bias, float* C)
{
    extern __shared__ char smc[];
    hgemm_body<0>(AHi, ALo, BHi, BLo, bias, C, nullptr, nullptr, smc);
}

// ---------------- scores (Q hoisted) + softmax + bf16 hi/lo P emit ----------------
#define SC_SMEM 215168u
__global__ __launch_bounds__(256)
void scores_mma(const __nv_bfloat16* __restrict__ QHi, const __nv_bfloat16* __restrict__ QLo,
                const __nv_bfloat16* __restrict__ KHi, const __nv_bfloat16* __restrict__ KLo,
                float* __restrict__ attn,
                __nv_bfloat16* __restrict__ PHi, __nv_bfloat16* __restrict__ PLo)
{
    extern __shared__ char smc[];
    const int tid = threadIdx.x, lane = tid & 31, wid = tid >> 5;
    const int wm = wid >> 2, wn = wid & 3;
    const int bh = blockIdx.y, q0 = blockIdx.x * 32;
    const uint32_t sb = smem_u32(smc);
    float* Ss = (float*)(smc + 82944);
    float* sinv = (float*)(smc + 215040);

    {
        int row = tid >> 3, ch = tid & 7;
        const size_t src = ((size_t)bh * L_ + q0 + row) * DK_ + ch * 8;
        cp16(sb + row * 144 + ch * 16, QHi + src);
        cp16(sb + 4608 + row * 144 + ch * 16, QLo + src);
    }
    auto loadK = [&](int cc, int buf) {
        uint32_t base = sb + 9216 + buf * 36864;
#pragma unroll
        for (int i = 0; i < 4; i++) {
            int idx = tid + i * 256;
            int row = idx >> 3, ch = idx & 7;
            const size_t src = ((size_t)bh * L_ + cc * 128 + row) * DK_ + ch * 8;
            cp16(base + row * 144 + ch * 16, KHi + src);
            cp16(base + 18432 + row * 144 + ch * 16, KLo + src);
        }
    };
    loadK(0, 0); CP_COMMIT();
    CP_WAIT0();
    __syncthreads();     // Q + K0 resident

    const uint32_t akb = (lane >> 4) * 16;
    const int bn8 = (lane & 16) ? 8 : 0;
    const uint32_t bkh = (lane & 8) ? 16 : 0;
    const int br = lane & 7;

    // hoist Q fragments (static across all K chunks)
    uint32_t qh[4][4], ql[4][4];
#pragma unroll
    for (int h = 0; h < 4; h++) {
        uint32_t aa = (uint32_t)(wm * 16 + (lane & 15)) * 144 + h * 32 + akb;
        ldsm4(qh[h], sb + aa);
        ldsm4(ql[h], sb + 4608 + aa);
    }

    for (int cc = 0; cc < 8; cc++) {
        if (cc < 7) { loadK(cc + 1, (cc + 1) & 1); CP_COMMIT(); CP_WAIT1(); }
        else        { CP_WAIT0(); }
        __syncthreads();
        uint32_t kHiB = sb + 9216 + (cc & 1) * 36864;
        uint32_t kLoB = kHiB + 18432;
        float acc[4][4];
#pragma unroll
        for (int i = 0; i < 4; i++)
#pragma unroll
            for (int q = 0; q < 4; q++) acc[i][q] = 0.f;
#pragma unroll
        for (int h = 0; h < 4; h++) {
            uint32_t bhi[2][4], blo[2][4];
#pragma unroll
            for (int g = 0; g < 2; g++) {
                uint32_t ba = (uint32_t)(wn * 32 + g * 16 + bn8 + br) * 144 + h * 32 + bkh;
                ldsm4(bhi[g], kHiB + ba);
                ldsm4(blo[g], kLoB + ba);
            }
#pragma unroll
            for (int g = 0; g < 2; g++)
#pragma unroll
                for (int j = 0; j < 2; j++) {
                    float* c = acc[g * 2 + j];
                    mma_bf16(c, qh[h], &bhi[g][j * 2]);
                    mma_bf16(c, qh[h], &blo[g][j * 2]);
                    mma_bf16(c, ql[h], &bhi[g][j * 2]);
                }
        }
#pragma unroll
        for (int nf = 0; nf < 4; nf++) {
            int col = cc * 128 + wn * 32 + nf * 8 + (lane & 3) * 2;
            int row = wm * 16 + (lane >> 2);
            *(float2*)(Ss + (size_t)row * 1032 + col) =
                make_float2(acc[nf][0] * 0.125f, acc[nf][1] * 0.125f);
            *(float2*)(Ss + (size_t)(row + 8) * 1032 + col) =
                make_float2(acc[nf][2] * 0.125f, acc[nf][3] * 0.125f);
        }
        __syncthreads();
    }

    int r = tid >> 3, g = tid & 7;
    float m = -1e30f;
    for (int c = g; c < 1024; c += 8) m = fmaxf(m, Ss[r * 1032 + c]);
#pragma unroll
    for (int o = 4; o; o >>= 1) m = fmaxf(m, __shfl_xor_sync(0xffffffffu, m, o));
    float s = 0.f;
    for (int c = g; c < 1024; c += 8) {
        float e = __expf(Ss[r * 1032 + c] - m);
        s += e;
        Ss[r * 1032 + c] = e;
    }
#pragma unroll
    for (int o = 4; o; o >>= 1) s += __shfl_xor_sync(0xffffffffu, s, o);
    if (g == 0) sinv[r] = 1.f / s;
    __syncthreads();

    // epilogue: normalized P -> fp32 attn (optional) + bf16 hi/lo P (always)
    float* Ap = attn ? attn + ((size_t)bh * L_ + q0) * L_ : nullptr;
    __nv_bfloat16* PhP = PHi + ((size_t)bh * L_ + q0) * L_;
    __nv_bfloat16* PlP = PLo + ((size_t)bh * L_ + q0) * L_;
    for (int idx = tid; idx < 32 * 1024 / 4; idx += 256) {
        int rr = idx >> 8, c4 = idx & 255;
        float inv = sinv[rr];
        float4 v;
        v.x = Ss[rr * 1032 + c4 * 4 + 0] * inv;
        v.y = Ss[rr * 1032 + c4 * 4 + 1] * inv;
        v.z = Ss[rr * 1032 + c4 * 4 + 2] * inv;
        v.w = Ss[rr * 1032 + c4 * 4 + 3] * inv;
        if (Ap) ((float4*)Ap)[idx] = v;
        uint32_t h0, l0, h1, l1;
        hilo_pack(v.x, v.y, h0, l0);
        hilo_pack(v.z, v.w, h1, l1);
        ((uint2*)PhP)[idx] = make_uint2(h0, h1);
        ((uint2*)PlP)[idx] = make_uint2(l0, l1);
    }
}

// ---------------- ctx = P @ V (HMMA): P bf16 hi/lo via cp.async, no conversion ----------------
// smem: Phi 0 (128*144) | Plo 18432 | Vhi 36864 (64*144) | Vlo 46080 ; total 55296
__global__ __launch_bounds__(256)
void ctx_mma(const __nv_bfloat16* __restrict__ PHi, const __nv_bfloat16* __restrict__ PLo,
             const __nv_bfloat16* __restrict__ VHi, const __nv_bfloat16* __restrict__ VLo,
             __nv_bfloat16* __restrict__ CHi, __nv_bfloat16* __restrict__ CLo)
{
    extern __shared__ char smc[];
    const int tid = threadIdx.x, lane = tid & 31, wid = tid >> 5;
    const int wm = wid >> 1, wn = wid & 1;
    const int bh = blockIdx.y, q0 = blockIdx.x * 128;
    const int b = bh >> 4, hh = bh & 15;
    const uint32_t sb = smem_u32(smc);

    float acc[2][4][4];
#pragma unroll
    for (int i = 0; i < 2; i++)
#pragma unroll
        for (int j = 0; j < 4; j++)
#pragma unroll
            for (int q = 0; q < 4; q++) acc[i][j][q] = 0.f;

    const uint32_t akb = (lane >> 4) * 16;
    const int vkoff = ((lane & 8) ? 8 : 0) + (lane & 7);
    const int vdoff = (lane & 16) ? 8 : 0;

    for (int k0 = 0; k0 < L_; k0 += 64) {
        // V chunk: 64 rows x 64 cols bf16 (hi+lo)
#pragma unroll
        for (int i = 0; i < 2; i++) {
            int idx = tid + i * 256;
            int row = idx >> 3, ch = idx & 7;
            const size_t src = ((size_t)bh * L_ + k0 + row) * DK_ + ch * 8;
            cp16(sb + 36864 + row * 144 + ch * 16, VHi + src);
            cp16(sb + 46080 + row * 144 + ch * 16, VLo + src);
        }
        // P chunk: 128 q-rows x 64 k bf16 (hi+lo) straight from gmem
#pragma unroll
        for (int i = 0; i < 4; i++) {
            int idx = tid + i * 256;
            int row = idx >> 3, ch = idx & 7;
            const size_t src = ((size_t)bh * L_ + q0 + row) * L_ + k0 + ch * 8;
            cp16(sb + row * 144 + ch * 16, PHi + src);
            cp16(sb + 18432 + row * 144 + ch * 16, PLo + src);
        }
        CP_COMMIT();
        CP_WAIT0();
        __syncthreads();
#pragma unroll
        for (int h = 0; h < 4; h++) {
            uint32_t vhi[2][4], vlo[2][4];
#pragma unroll
            for (int g = 0; g < 2; g++) {
                uint32_t va = (uint32_t)(h * 16 + vkoff) * 144
                            + (uint32_t)(wn * 32 + g * 16 + vdoff) * 2;
                ldsm4t(vhi[g], sb + 36864 + va);
                ldsm4t(vlo[g], sb + 46080 + va);
            }
#pragma unroll
            for (int mf = 0; mf < 2; mf++) {
                uint32_t ah[4], al[4];
                uint32_t aa = (uint32_t)(wm * 32 + mf * 16 + (lane & 15)) * 144 + h * 32 + akb;
                ldsm4(ah, sb + aa);
                ldsm4(al, sb + 18432 + aa);
#pragma unroll
                for (int g = 0; g < 2; g++)
#pragma unroll
                    for (int j = 0; j < 2; j++) {
                        float* c = acc[mf][g * 2 + j];
                        mma_bf16(c, ah, &vhi[g][j * 2]);
                        mma_bf16(c, ah, &vlo[g][j * 2]);
                        mma_bf16(c, al, &vhi[g][j * 2]);
                    }
            }
        }
        __syncthreads();
    }

#pragma unroll
    for (int mf = 0; mf < 2; mf++)
#pragma unroll
        for (int nf = 0; nf < 4; nf++) {
            int d = wn * 32 + nf * 8 + (lane & 3) * 2;
            int q = q0 + wm * 32 + mf * 16 + (lane >> 2);
#pragma unroll
            for (int half = 0; half < 2; half++) {
                int qq = q + half * 8;
                size_t dst = ((size_t)(b * L_ + qq)) * D_ + hh * DK_ + d;
                uint32_t hi, lo;
                hilo_pack(acc[mf][nf][half * 2 + 0], acc[mf][nf][half * 2 + 1], hi, lo);
                *(uint32_t*)(CHi + dst) = hi;
                *(uint32_t*)(CLo + dst) = lo;
            }
        }
}

// ---------------------------------------------------------------------------
extern "C" void kernel_launch(void* const* d_in, const int* in_sizes, int n_in,
                              void* d_out, int out_size)
{
    const float* hidden = (const float*)d_in[0];
    const float* key    = (const float*)d_in[1];
    const float* ctxv   = (const float*)d_in[2];
    const float* Wq = (const float*)d_in[3];
    const float* bq = (const float*)d_in[4];
    const float* Wk = (const float*)d_in[5];
    const float* bk = (const float*)d_in[6];
    const float* Wv = (const float*)d_in[7];
    const float* bv = (const float*)d_in[8];
    const float* Wo = (const float*)d_in[9];
    const float* bo = (const float*)d_in[10];

    float *op;
    cudaGetSymbolAddress((void**)&op, g_outs);
    __nv_bfloat16 *qHi,*qLo,*kHi,*kLo,*vHi,*vLo,*pHi,*pLo;
    cudaGetSymbolAddress((void**)&qHi, g_qHi); cudaGetSymbolAddress((void**)&qLo, g_qLo);
    cudaGetSymbolAddress((void**)&kHi, g_kHi); cudaGetSymbolAddress((void**)&kLo, g_kLo);
    cudaGetSymbolAddress((void**)&vHi, g_vHi); cudaGetSymbolAddress((void**)&vLo, g_vLo);
    cudaGetSymbolAddress((void**)&pHi, g_pHi); cudaGetSymbolAddress((void**)&pLo, g_pLo);
    __nv_bfloat16 *hidHi,*hidLo,*keyHi,*keyLo,*cvHi,*cvLo,*ctxHi,*ctxLo;
    cudaGetSymbolAddress((void**)&hidHi, g_hidHi); cudaGetSymbolAddress((void**)&hidLo, g_hidLo);
    cudaGetSymbolAddress((void**)&keyHi, g_keyHi); cudaGetSymbolAddress((void**)&keyLo, g_keyLo);
    cudaGetSymbolAddress((void**)&cvHi,  g_cvHi);  cudaGetSymbolAddress((void**)&cvLo,  g_cvLo);
    cudaGetSymbolAddress((void**)&ctxHi, g_ctxHi); cudaGetSymbolAddress((void**)&ctxLo, g_ctxLo);
    __nv_bfloat16 *WqHi,*WqLo,*WkHi,*WkLo,*WvHi,*WvLo,*WoHi,*WoLo;
    cudaGetSymbolAddress((void**)&WqHi, g_WqHi); cudaGetSymbolAddress((void**)&WqLo, g_WqLo);
    cudaGetSymbolAddress((void**)&WkHi, g_WkHi); cudaGetSymbolAddress((void**)&WkLo, g_WkLo);
    cudaGetSymbolAddress((void**)&WvHi, g_WvHi); cudaGetSymbolAddress((void**)&WvLo, g_WvLo);
    cudaGetSymbolAddress((void**)&WoHi, g_WoHi); cudaGetSymbolAddress((void**)&WoLo, g_WoLo);

    const size_t out_elems  = (size_t)B_ * L_ * D_;
    const size_t attn_elems = (size_t)B_ * H_ * L_ * L_;
    float* outp;
    float* attnp;   // nullptr -> fp32 attn not needed
    if ((size_t)out_size >= out_elems + attn_elems) {
        outp  = (float*)d_out;
        attnp = (float*)d_out + out_elems;
    } else if ((size_t)out_size == attn_elems) {
        outp  = op;
        attnp = (float*)d_out;
    } else {
        outp  = (float*)d_out;
        attnp = nullptr;          // attn not checked; skip fp32 write
    }

    cudaFuncSetAttribute(hgemm_qkv, cudaFuncAttributeMaxDynamicSharedMemorySize, 2 * HG_ST);
    cudaFuncSetAttribute(hgemm_out, cudaFuncAttributeMaxDynamicSharedMemorySize, 2 * HG_ST);
    cudaFuncSetAttribute(scores_mma, cudaFuncAttributeMaxDynamicSharedMemorySize, SC_SMEM);
    cudaFuncSetAttribute(ctx_mma, cudaFuncAttributeMaxDynamicSharedMemorySize, 55296);

    const int n4 = M_ * D_ / 4;
    split3_kernel<<<dim3(n4 / 256, 3), 256>>>(
        (const float4*)hidden, (const float4*)key, (const float4*)ctxv,
        (bf4*)hidHi, (bf4*)hidLo, (bf4*)keyHi, (bf4*)keyLo, (bf4*)cvHi, (bf4*)cvLo, n4);
    tsplit4_kernel<<<dim3(32, 32, 4), dim3(32, 8)>>>(
        Wq, Wk, Wv, Wo, WqHi, WqLo, WkHi, WkLo, WvHi, WvLo, WoHi, WoLo);

    hgemm_qkv<<<dim3(8, 64, 3), 256, 2 * HG_ST>>>(
        hidHi, hidLo, keyHi, keyLo, cvHi, cvLo,
        WqHi, WqLo, WkHi, WkLo, WvHi, WvLo,
        bq, bk, bv, qHi, qLo, kHi, kLo, vHi, vLo);

    scores_mma<<<dim3(32, 128), 256, SC_SMEM>>>(qHi, qLo, kHi, kLo, attnp, pHi, pLo);

    ctx_mma<<<dim3(8, 128), 256, 55296>>>(pHi, pLo, vHi, vLo, ctxHi, ctxLo);

    hgemm_out<<<dim3(8, 64), 256, 2 * HG_ST>>>(ctxHi, ctxLo, WoHi, WoLo, bo, outp);
}

// round 15
// speedup vs baseline: 1.0301x; 1.0281x over previous
#include <cuda_runtime.h>
#include <cuda_bf16.h>
#include <cstdint>

#define B_  8
#define L_  1024
#define D_  1024
#define H_  16
#define DK_ 64
#define M_  (B_*L_)   // 8192

// ---------------- scratch (device globals) ----------------
__device__ __nv_bfloat16 g_qHi[M_*D_], g_qLo[M_*D_];   // [B,H,L,64]
__device__ __nv_bfloat16 g_kHi[M_*D_], g_kLo[M_*D_];
__device__ __nv_bfloat16 g_vHi[M_*D_], g_vLo[M_*D_];
__device__ float g_attn[134217728];
__device__ float g_outs[M_*D_];
__device__ __nv_bfloat16 g_hidHi[M_*D_], g_hidLo[M_*D_];
__device__ __nv_bfloat16 g_keyHi[M_*D_], g_keyLo[M_*D_];
__device__ __nv_bfloat16 g_cvHi [M_*D_], g_cvLo [M_*D_];
__device__ __nv_bfloat16 g_ctxHi[M_*D_], g_ctxLo[M_*D_];
__device__ __nv_bfloat16 g_WqHi[D_*D_], g_WqLo[D_*D_];
__device__ __nv_bfloat16 g_WkHi[D_*D_], g_WkLo[D_*D_];
__device__ __nv_bfloat16 g_WvHi[D_*D_], g_WvLo[D_*D_];
__device__ __nv_bfloat16 g_WoHi[D_*D_], g_WoLo[D_*D_];

// ---------------- helpers ----------------
__device__ __forceinline__ uint32_t smem_u32(const void* p) {
    return (uint32_t)__cvta_generic_to_shared((void*)p);
}
#define CP_COMMIT() asm volatile("cp.async.commit_group;" ::: "memory")
#define CP_WAIT0()  asm volatile("cp.async.wait_group 0;" ::: "memory")
#define CP_WAIT1()  asm volatile("cp.async.wait_group 1;" ::: "memory")
__device__ __forceinline__ void cp16(uint32_t dst, const void* src) {
    asm volatile("cp.async.cg.shared.global [%0], [%1], 16;" :: "r"(dst), "l"(src));
}
__device__ __forceinline__ void ldsm4(uint32_t* r, uint32_t a) {
    asm volatile("ldmatrix.sync.aligned.m8n8.x4.shared.b16 {%0,%1,%2,%3}, [%4];"
        : "=r"(r[0]), "=r"(r[1]), "=r"(r[2]), "=r"(r[3]) : "r"(a));
}
__device__ __forceinline__ void ldsm4t(uint32_t* r, uint32_t a) {
    asm volatile("ldmatrix.sync.aligned.m8n8.x4.trans.shared.b16 {%0,%1,%2,%3}, [%4];"
        : "=r"(r[0]), "=r"(r[1]), "=r"(r[2]), "=r"(r[3]) : "r"(a));
}
__device__ __forceinline__ void mma_bf16(float* c, const uint32_t* a, const uint32_t* b) {
    asm volatile("mma.sync.aligned.m16n8k16.row.col.f32.bf16.bf16.f32 "
        "{%0,%1,%2,%3}, {%4,%5,%6,%7}, {%8,%9}, {%0,%1,%2,%3};"
        : "+f"(c[0]), "+f"(c[1]), "+f"(c[2]), "+f"(c[3])
        : "r"(a[0]), "r"(a[1]), "r"(a[2]), "r"(a[3]), "r"(b[0]), "r"(b[1]));
}
__device__ __forceinline__ void hilo_pack(float a, float b, uint32_t& hi, uint32_t& lo) {
    __nv_bfloat16 ha = __float2bfloat16(a), hb = __float2bfloat16(b);
    __nv_bfloat16 la = __float2bfloat16(a - __bfloat162float(ha));
    __nv_bfloat16 lb = __float2bfloat16(b - __bfloat162float(hb));
    hi = (uint32_t)__bfloat16_as_ushort(ha) | ((uint32_t)__bfloat16_as_ushort(hb) << 16);
    lo = (uint32_t)__bfloat16_as_ushort(la) | ((uint32_t)__bfloat16_as_ushort(lb) << 16);
}

// ---------------- prep: fp32 -> bf16 hi/lo (batched) ----------------
struct __align__(8) bf4 { __nv_bfloat16 x, y, z, w; };
__global__ void split3_kernel(const float4* __restrict__ X0, const float4* __restrict__ X1,
                              const float4* __restrict__ X2,
                              bf4* __restrict__ H0, bf4* __restrict__ L0,
                              bf4* __restrict__ H1, bf4* __restrict__ L1,
                              bf4* __restrict__ H2, bf4* __restrict__ L2, int n4)
{
    const float4* X; bf4 *Hi, *Lo;
    if (blockIdx.y == 0)      { X = X0; Hi = H0; Lo = L0; }
    else if (blockIdx.y == 1) { X = X1; Hi = H1; Lo = L1; }
    else                      { X = X2; Hi = H2; Lo = L2; }
    int i = blockIdx.x * 256 + threadIdx.x;
    if (i >= n4) return;
    float4 v = X[i];
    bf4 h, l;
    h.x = __float2bfloat16(v.x); l.x = __float2bfloat16(v.x - __bfloat162float(h.x));
    h.y = __float2bfloat16(v.y); l.y = __float2bfloat16(v.y - __bfloat162float(h.y));
    h.z = __float2bfloat16(v.z); l.z = __float2bfloat16(v.z - __bfloat162float(h.z));
    h.w = __float2bfloat16(v.w); l.w = __float2bfloat16(v.w - __bfloat162float(h.w));
    Hi[i] = h; Lo[i] = l;
}
__global__ void tsplit4_kernel(const float* __restrict__ W0, const float* __restrict__ W1,
                               const float* __restrict__ W2, const float* __restrict__ W3,
                               __nv_bfloat16* __restrict__ H0, __nv_bfloat16* __restrict__ L0,
                               __nv_bfloat16* __restrict__ H1, __nv_bfloat16* __restrict__ L1,
                               __nv_bfloat16* __restrict__ H2, __nv_bfloat16* __restrict__ L2,
                               __nv_bfloat16* __restrict__ H3, __nv_bfloat16* __restrict__ L3)
{
    const float* W; __nv_bfloat16 *Hi, *Lo;
    int z = blockIdx.z;
    if (z == 0)      { W = W0; Hi = H0; Lo = L0; }
    else if (z == 1) { W = W1; Hi = H1; Lo = L1; }
    else if (z == 2) { W = W2; Hi = H2; Lo = L2; }
    else             { W = W3; Hi = H3; Lo = L3; }
    __shared__ float t[32][33];
    int bx = blockIdx.x * 32, by = blockIdx.y * 32;
    int x = threadIdx.x, y = threadIdx.y;
#pragma unroll
    for (int i = 0; i < 32; i += 8)
        t[y + i][x] = W[(size_t)(by + y + i) * D_ + bx + x];
    __syncthreads();
#pragma unroll
    for (int i = 0; i < 32; i += 8) {
        float v = t[x][y + i];
        __nv_bfloat16 h = __float2bfloat16(v);
        __nv_bfloat16 l = __float2bfloat16(v - __bfloat162float(h));
        size_t o = (size_t)(bx + y + i) * D_ + by + x;
        Hi[o] = h; Lo[o] = l;
    }
}

// ---------------- HMMA GEMM: 128x128 tile, 256 threads, pass-major MMA order ----------------
#define HG_ST 40960u
template <int MODE>
__device__ __forceinline__
void hgemm_body(const __nv_bfloat16* __restrict__ AHi, const __nv_bfloat16* __restrict__ ALo,
                const __nv_bfloat16* __restrict__ BHi, const __nv_bfloat16* __restrict__ BLo,
                const float* __restrict__ bias,
                float* __restrict__ C, __nv_bfloat16* __restrict__ CHi, __nv_bfloat16* __restrict__ CLo,
                char* smc)
{
    const int tid = threadIdx.x, lane = tid & 31, wid = tid >> 5;
    const int wm = wid >> 2, wn = wid & 3;
    const int n0 = blockIdx.x * 128, m0 = blockIdx.y * 128;
    const uint32_t sb = smem_u32(smc);

    const int lr = tid >> 2, lc = tid & 3;
    const int arow = wm * 64 + (lane & 15);
    const uint32_t akb = (lane >> 4) * 16;
    const int bn8 = (lane & 16) ? 8 : 0;
    const uint32_t bkh = (lane & 8) ? 16 : 0;
    const int br = lane & 7;

    float acc[4][4][4];
#pragma unroll
    for (int i = 0; i < 4; i++)
#pragma unroll
        for (int j = 0; j < 4; j++)
#pragma unroll
            for (int q = 0; q < 4; q++) acc[i][j][q] = 0.f;

    auto load_stage = [&](int s, int buf) {
        uint32_t base = sb + buf * HG_ST;
        int k0 = s * 32;
#pragma unroll
        for (int half = 0; half < 2; half++) {
            int row = lr + half * 64;
            uint32_t doff = row * 80 + lc * 16;
            cp16(base + doff,          AHi + (size_t)(m0 + row) * D_ + k0 + lc * 8);
            cp16(base + 10240 + doff,  ALo + (size_t)(m0 + row) * D_ + k0 + lc * 8);
            cp16(base + 20480 + doff,  BHi + (size_t)(n0 + row) * D_ + k0 + lc * 8);
            cp16(base + 30720 + doff,  BLo + (size_t)(n0 + row) * D_ + k0 + lc * 8);
        }
    };

    load_stage(0, 0); CP_COMMIT();

    for (int s = 0; s < 32; s++) {
        if (s < 31) { load_stage(s + 1, (s + 1) & 1); CP_COMMIT(); CP_WAIT1(); }
        else        { CP_WAIT0(); }
        __syncthreads();
        uint32_t aHiB = sb + (s & 1) * HG_ST;
        uint32_t aLoB = aHiB + 10240, bHiB = aHiB + 20480, bLoB = aHiB + 30720;
#pragma unroll
        for (int h = 0; h < 2; h++) {
            uint32_t bhi[2][4], blo[2][4];
#pragma unroll
            for (int g = 0; g < 2; g++) {
                uint32_t ba = (uint32_t)(wn * 32 + g * 16 + bn8 + br) * 80 + h * 32 + bkh;
                ldsm4(bhi[g], bHiB + ba);
                ldsm4(blo[g], bLoB + ba);
            }
#pragma unroll
            for (int mf = 0; mf < 4; mf++) {
                uint32_t ah[4], al[4];
                uint32_t aa = (uint32_t)(arow + mf * 16) * 80 + h * 32 + akb;
                ldsm4(ah, aHiB + aa);
                ldsm4(al, aLoB + aa);
                // pass-major: consecutive MMAs hit distinct accumulators
#pragma unroll
                for (int g = 0; g < 2; g++)
#pragma unroll
                    for (int j = 0; j < 2; j++)
                        mma_bf16(acc[mf][g * 2 + j], ah, &bhi[g][j * 2]);
#pragma unroll
                for (int g = 0; g < 2; g++)
#pragma unroll
                    for (int j = 0; j < 2; j++)
                        mma_bf16(acc[mf][g * 2 + j], ah, &blo[g][j * 2]);
#pragma unroll
                for (int g = 0; g < 2; g++)
#pragma unroll
                    for (int j = 0; j < 2; j++)
                        mma_bf16(acc[mf][g * 2 + j], al, &bhi[g][j * 2]);
            }
        }
        __syncthreads();
    }

#pragma unroll
    for (int mf = 0; mf < 4; mf++)
#pragma unroll
        for (int nf = 0; nf < 4; nf++) {
            int col = n0 + wn * 32 + nf * 8 + (lane & 3) * 2;
            float b0 = __ldg(bias + col), b1 = __ldg(bias + col + 1);
            int r0 = m0 + wm * 64 + mf * 16 + (lane >> 2);
#pragma unroll
            for (int half = 0; half < 2; half++) {
                int r = r0 + half * 8;
                float v0 = acc[mf][nf][half * 2 + 0] + b0;
                float v1 = acc[mf][nf][half * 2 + 1] + b1;
                if (MODE == 0) {
                    *(float2*)(C + (size_t)r * D_ + col) = make_float2(v0, v1);
                } else {
                    int hh = col >> 6, d = col & 63;
                    int bb = r >> 10, l = r & 1023;
                    size_t dst = (((size_t)(bb * H_ + hh) * L_ + l) * DK_) + d;
                    uint32_t hi, lo;
                    hilo_pack(v0, v1, hi, lo);
                    *(uint32_t*)(CHi + dst) = hi;
                    *(uint32_t*)(CLo + dst) = lo;
                }
            }
        }
}

__global__ __launch_bounds__(256)
void hgemm_qkv(const __nv_bfloat16* hidHi, const __nv_bfloat16* hidLo,
               const __nv_bfloat16* keyHi, const __nv_bfloat16* keyLo,
               const __nv_bfloat16* cvHi,  const __nv_bfloat16* cvLo,
               const __nv_bfloat16* WqHi, const __nv_bfloat16* WqLo,
               const __nv_bfloat16* WkHi, const __nv_bfloat16* WkLo,
               const __nv_bfloat16* WvHi, const __nv_bfloat16* WvLo,
               const float* bq, const float* bk, const float* bv,
               __nv_bfloat16* qHi, __nv_bfloat16* qLo,
               __nv_bfloat16* kHi, __nv_bfloat16* kLo,
               __nv_bfloat16* vHi, __nv_bfloat16* vLo)
{
    extern __shared__ char smc[];
    const __nv_bfloat16 *AHi, *ALo, *BHi, *BLo;
    const float* bias;
    __nv_bfloat16 *CHi, *CLo;
    int z = blockIdx.z;
    if (z == 0)      { AHi = hidHi; ALo = hidLo; BHi = WqHi; BLo = WqLo; bias = bq; CHi = qHi; CLo = qLo; }
    else if (z == 1) { AHi = keyHi; ALo = keyLo; BHi = WkHi; BLo = WkLo; bias = bk; CHi = kHi; CLo = kLo; }
    else             { AHi = cvHi;  ALo = cvLo;  BHi = WvHi; BLo = WvLo; bias = bv; CHi = vHi; CLo = vLo; }
    hgemm_body<1>(AHi, ALo, BHi, BLo, bias, nullptr, CHi, CLo, smc);
}

__global__ __launch_bounds__(256)
void hgemm_out(const __nv_bfloat16* AHi, const __nv_bfloat16* ALo,
               const __nv_bfloat16* BHi, const __nv_bfloat16* BLo,
               const float* bias, float* C)
{
    extern __shared__ char smc[];
    hgemm_body<0>(AHi, ALo, BHi, BLo, bias, C, nullptr, nullptr, smc);
}

// ---------------- scores (Q hoisted, pass-major MMA order) + softmax ----------------
#define SC_SMEM 215168u
__global__ __launch_bounds__(256)
void scores_mma(const __nv_bfloat16* __restrict__ QHi, const __nv_bfloat16* __restrict__ QLo,
                const __nv_bfloat16* __restrict__ KHi, const __nv_bfloat16* __restrict__ KLo,
                float* __restrict__ attn)
{
    extern __shared__ char smc[];
    const int tid = threadIdx.x, lane = tid & 31, wid = tid >> 5;
    const int wm = wid >> 2, wn = wid & 3;
    const int bh = blockIdx.y, q0 = blockIdx.x * 32;
    const uint32_t sb = smem_u32(smc);
    float* Ss = (float*)(smc + 82944);
    float* sinv = (float*)(smc + 215040);

    {
        int row = tid >> 3, ch = tid & 7;
        const size_t src = ((size_t)bh * L_ + q0 + row) * DK_ + ch * 8;
        cp16(sb + row * 144 + ch * 16, QHi + src);
        cp16(sb + 4608 + row * 144 + ch * 16, QLo + src);
    }
    auto loadK = [&](int cc, int buf) {
        uint32_t base = sb + 9216 + buf * 36864;
#pragma unroll
        for (int i = 0; i < 4; i++) {
            int idx = tid + i * 256;
            int row = idx >> 3, ch = idx & 7;
            const size_t src = ((size_t)bh * L_ + cc * 128 + row) * DK_ + ch * 8;
            cp16(base + row * 144 + ch * 16, KHi + src);
            cp16(base + 18432 + row * 144 + ch * 16, KLo + src);
        }
    };
    loadK(0, 0); CP_COMMIT();
    CP_WAIT0();
    __syncthreads();     // Q + K0 resident

    const uint32_t akb = (lane >> 4) * 16;
    const int bn8 = (lane & 16) ? 8 : 0;
    const uint32_t bkh = (lane & 8) ? 16 : 0;
    const int br = lane & 7;

    uint32_t qh[4][4], ql[4][4];
#pragma unroll
    for (int h = 0; h < 4; h++) {
        uint32_t aa = (uint32_t)(wm * 16 + (lane & 15)) * 144 + h * 32 + akb;
        ldsm4(qh[h], sb + aa);
        ldsm4(ql[h], sb + 4608 + aa);
    }

    for (int cc = 0; cc < 8; cc++) {
        if (cc < 7) { loadK(cc + 1, (cc + 1) & 1); CP_COMMIT(); CP_WAIT1(); }
        else        { CP_WAIT0(); }
        __syncthreads();
        uint32_t kHiB = sb + 9216 + (cc & 1) * 36864;
        uint32_t kLoB = kHiB + 18432;
        float acc[4][4];
#pragma unroll
        for (int i = 0; i < 4; i++)
#pragma unroll
            for (int q = 0; q < 4; q++) acc[i][q] = 0.f;
#pragma unroll
        for (int h = 0; h < 4; h++) {
            uint32_t bhi[2][4], blo[2][4];
#pragma unroll
            for (int g = 0; g < 2; g++) {
                uint32_t ba = (uint32_t)(wn * 32 + g * 16 + bn8 + br) * 144 + h * 32 + bkh;
                ldsm4(bhi[g], kHiB + ba);
                ldsm4(blo[g], kLoB + ba);
            }
            // pass-major: 4 independent accs per pass
#pragma unroll
            for (int g = 0; g < 2; g++)
#pragma unroll
                for (int j = 0; j < 2; j++)
                    mma_bf16(acc[g * 2 + j], qh[h], &bhi[g][j * 2]);
#pragma unroll
            for (int g = 0; g < 2; g++)
#pragma unroll
                for (int j = 0; j < 2; j++)
                    mma_bf16(acc[g * 2 + j], qh[h], &blo[g][j * 2]);
#pragma unroll
            for (int g = 0; g < 2; g++)
#pragma unroll
                for (int j = 0; j < 2; j++)
                    mma_bf16(acc[g * 2 + j], ql[h], &bhi[g][j * 2]);
        }
#pragma unroll
        for (int nf = 0; nf < 4; nf++) {
            int col = cc * 128 + wn * 32 + nf * 8 + (lane & 3) * 2;
            int row = wm * 16 + (lane >> 2);
            *(float2*)(Ss + (size_t)row * 1032 + col) =
                make_float2(acc[nf][0] * 0.125f, acc[nf][1] * 0.125f);
            *(float2*)(Ss + (size_t)(row + 8) * 1032 + col) =
                make_float2(acc[nf][2] * 0.125f, acc[nf][3] * 0.125f);
        }
        __syncthreads();
    }

    int r = tid >> 3, g = tid & 7;
    float m = -1e30f;
    for (int c = g; c < 1024; c += 8) m = fmaxf(m, Ss[r * 1032 + c]);
#pragma unroll
    for (int o = 4; o; o >>= 1) m = fmaxf(m, __shfl_xor_sync(0xffffffffu, m, o));
    float s = 0.f;
    for (int c = g; c < 1024; c += 8) {
        float e = __expf(Ss[r * 1032 + c] - m);
        s += e;
        Ss[r * 1032 + c] = e;
    }
#pragma unroll
    for (int o = 4; o; o >>= 1) s += __shfl_xor_sync(0xffffffffu, s, o);
    if (g == 0) sinv[r] = 1.f / s;
    __syncthreads();

    float* Ap = attn + ((size_t)bh * L_ + q0) * L_;
    for (int idx = tid; idx < 32 * 1024 / 4; idx += 256) {
        int rr = idx >> 8, c4 = idx & 255;
        float inv = sinv[rr];
        float4 v;
        v.x = Ss[rr * 1032 + c4 * 4 + 0] * inv;
        v.y = Ss[rr * 1032 + c4 * 4 + 1] * inv;
        v.z = Ss[rr * 1032 + c4 * 4 + 2] * inv;
        v.w = Ss[rr * 1032 + c4 * 4 + 3] * inv;
        ((float4*)Ap)[idx] = v;
    }
}

// ---------------- ctx = attn @ V (R3 structure, pass-major MMA order) ----------------
__global__ __launch_bounds__(256)
void ctx_mma(const float* __restrict__ attn,
             const __nv_bfloat16* __restrict__ VHi, const __nv_bfloat16* __restrict__ VLo,
             __nv_bfloat16* __restrict__ CHi, __nv_bfloat16* __restrict__ CLo)
{
    extern __shared__ char smc[];
    const int tid = threadIdx.x, lane = tid & 31, wid = tid >> 5;
    const int wm = wid >> 1, wn = wid & 1;
    const int bh = blockIdx.y, q0 = blockIdx.x * 128;
    const int b = bh >> 4, hh = bh & 15;
    const uint32_t sb = smem_u32(smc);

    float acc[2][4][4];
#pragma unroll
    for (int i = 0; i < 2; i++)
#pragma unroll
        for (int j = 0; j < 4; j++)
#pragma unroll
            for (int q = 0; q < 4; q++) acc[i][j][q] = 0.f;

    const uint32_t akb = (lane >> 4) * 16;
    const int vkoff = ((lane & 8) ? 8 : 0) + (lane & 7);
    const int vdoff = (lane & 16) ? 8 : 0;

    for (int k0 = 0; k0 < L_; k0 += 64) {
#pragma unroll
        for (int i = 0; i < 2; i++) {
            int idx = tid + i * 256;
            int row = idx >> 3, ch = idx & 7;
            const size_t src = ((size_t)bh * L_ + k0 + row) * DK_ + ch * 8;
            cp16(sb + 36864 + row * 144 + ch * 16, VHi + src);
            cp16(sb + 46080 + row * 144 + ch * 16, VLo + src);
        }
        CP_COMMIT();
#pragma unroll
        for (int i = 0; i < 4; i++) {
            int task = tid + i * 256;
            int rr = task >> 3, ch = task & 7;
            const float* src = attn + ((size_t)bh * L_ + q0 + rr) * L_ + k0 + ch * 8;
            float4 v0 = *(const float4*)src;
            float4 v1 = *(const float4*)(src + 4);
            uint4 hi, lo;
            hilo_pack(v0.x, v0.y, hi.x, lo.x);
            hilo_pack(v0.z, v0.w, hi.y, lo.y);
            hilo_pack(v1.x, v1.y, hi.z, lo.z);
            hilo_pack(v1.z, v1.w, hi.w, lo.w);
            *(uint4*)(smc + rr * 144 + ch * 16) = hi;
            *(uint4*)(smc + 18432 + rr * 144 + ch * 16) = lo;
        }
        CP_WAIT0();
        __syncthreads();
#pragma unroll
        for (int h = 0; h < 4; h++) {
            uint32_t vhi[2][4], vlo[2][4];
#pragma unroll
            for (int g = 0; g < 2; g++) {
                uint32_t va = (uint32_t)(h * 16 + vkoff) * 144
                            + (uint32_t)(wn * 32 + g * 16 + vdoff) * 2;
                ldsm4t(vhi[g], sb + 36864 + va);
                ldsm4t(vlo[g], sb + 46080 + va);
            }
#pragma unroll
            for (int mf = 0; mf < 2; mf++) {
                uint32_t ah[4], al[4];
                uint32_t aa = (uint32_t)(wm * 32 + mf * 16 + (lane & 15)) * 144 + h * 32 + akb;
                ldsm4(ah, sb + aa);
                ldsm4(al, sb + 18432 + aa);
                // pass-major: 4 independent accs per pass
#pragma unroll
                for (int g = 0; g < 2; g++)
#pragma unroll
                    for (int j = 0; j < 2; j++)
                        mma_bf16(acc[mf][g * 2 + j], ah, &vhi[g][j * 2]);
#pragma unroll
                for (int g = 0; g < 2; g++)
#pragma unroll
                    for (int j = 0; j < 2; j++)
                        mma_bf16(acc[mf][g * 2 + j], ah, &vlo[g][j * 2]);
#pragma unroll
                for (int g = 0; g < 2; g++)
#pragma unroll
                    for (int j = 0; j < 2; j++)
                        mma_bf16(acc[mf][g * 2 + j], al, &vhi[g][j * 2]);
            }
        }
        __syncthreads();
    }

#pragma unroll
    for (int mf = 0; mf < 2; mf++)
#pragma unroll
        for (int nf = 0; nf < 4; nf++) {
            int d = wn * 32 + nf * 8 + (lane & 3) * 2;
            int q = q0 + wm * 32 + mf * 16 + (lane >> 2);
#pragma unroll
            for (int half = 0; half < 2; half++) {
                int qq = q + half * 8;
                size_t dst = ((size_t)(b * L_ + qq)) * D_ + hh * DK_ + d;
                uint32_t hi, lo;
                hilo_pack(acc[mf][nf][half * 2 + 0], acc[mf][nf][half * 2 + 1], hi, lo);
                *(uint32_t*)(CHi + dst) = hi;
                *(uint32_t*)(CLo + dst) = lo;
            }
        }
}

// ---------------------------------------------------------------------------
extern "C" void kernel_launch(void* const* d_in, const int* in_sizes, int n_in,
                              void* d_out, int out_size)
{
    const float* hidden = (const float*)d_in[0];
    const float* key    = (const float*)d_in[1];
    const float* ctxv   = (const float*)d_in[2];
    const float* Wq = (const float*)d_in[3];
    const float* bq = (const float*)d_in[4];
    const float* Wk = (const float*)d_in[5];
    const float* bk = (const float*)d_in[6];
    const float* Wv = (const float*)d_in[7];
    const float* bv = (const float*)d_in[8];
    const float* Wo = (const float*)d_in[9];
    const float* bo = (const float*)d_in[10];

    float *ap, *op;
    cudaGetSymbolAddress((void**)&ap, g_attn);
    cudaGetSymbolAddress((void**)&op, g_outs);
    __nv_bfloat16 *qHi,*qLo,*kHi,*kLo,*vHi,*vLo;
    cudaGetSymbolAddress((void**)&qHi, g_qHi); cudaGetSymbolAddress((void**)&qLo, g_qLo);
    cudaGetSymbolAddress((void**)&kHi, g_kHi); cudaGetSymbolAddress((void**)&kLo, g_kLo);
    cudaGetSymbolAddress((void**)&vHi, g_vHi); cudaGetSymbolAddress((void**)&vLo, g_vLo);
    __nv_bfloat16 *hidHi,*hidLo,*keyHi,*keyLo,*cvHi,*cvLo,*ctxHi,*ctxLo;
    cudaGetSymbolAddress((void**)&hidHi, g_hidHi); cudaGetSymbolAddress((void**)&hidLo, g_hidLo);
    cudaGetSymbolAddress((void**)&keyHi, g_keyHi); cudaGetSymbolAddress((void**)&keyLo, g_keyLo);
    cudaGetSymbolAddress((void**)&cvHi,  g_cvHi);  cudaGetSymbolAddress((void**)&cvLo,  g_cvLo);
    cudaGetSymbolAddress((void**)&ctxHi, g_ctxHi); cudaGetSymbolAddress((void**)&ctxLo, g_ctxLo);
    __nv_bfloat16 *WqHi,*WqLo,*WkHi,*WkLo,*WvHi,*WvLo,*WoHi,*WoLo;
    cudaGetSymbolAddress((void**)&WqHi, g_WqHi); cudaGetSymbolAddress((void**)&WqLo, g_WqLo);
    cudaGetSymbolAddress((void**)&WkHi, g_WkHi); cudaGetSymbolAddress((void**)&WkLo, g_WkLo);
    cudaGetSymbolAddress((void**)&WvHi, g_WvHi); cudaGetSymbolAddress((void**)&WvLo, g_WvLo);
    cudaGetSymbolAddress((void**)&WoHi, g_WoHi); cudaGetSymbolAddress((void**)&WoLo, g_WoLo);

    const size_t out_elems  = (size_t)B_ * L_ * D_;
    const size_t attn_elems = (size_t)B_ * H_ * L_ * L_;
    float* outp;
    float* attnp;
    if ((size_t)out_size >= out_elems + attn_elems) {
        outp  = (float*)d_out;
        attnp = (float*)d_out + out_elems;
    } else if ((size_t)out_size == attn_elems) {
        outp  = op;
        attnp = (float*)d_out;
    } else {
        outp  = (float*)d_out;
        attnp = ap;
    }

    cudaFuncSetAttribute(hgemm_qkv, cudaFuncAttributeMaxDynamicSharedMemorySize, 2 * HG_ST);
    cudaFuncSetAttribute(hgemm_out, cudaFuncAttributeMaxDynamicSharedMemorySize, 2 * HG_ST);
    cudaFuncSetAttribute(scores_mma, cudaFuncAttributeMaxDynamicSharedMemorySize, SC_SMEM);
    cudaFuncSetAttribute(ctx_mma, cudaFuncAttributeMaxDynamicSharedMemorySize, 55296);

    const int n4 = M_ * D_ / 4;
    split3_kernel<<<dim3(n4 / 256, 3), 256>>>(
        (const float4*)hidden, (const float4*)key, (const float4*)ctxv,
        (bf4*)hidHi, (bf4*)hidLo, (bf4*)keyHi, (bf4*)keyLo, (bf4*)cvHi, (bf4*)cvLo, n4);
    tsplit4_kernel<<<dim3(32, 32, 4), dim3(32, 8)>>>(
        Wq, Wk, Wv, Wo, WqHi, WqLo, WkHi, WkLo, WvHi, WvLo, WoHi, WoLo);

    hgemm_qkv<<<dim3(8, 64, 3), 256, 2 * HG_ST>>>(
        hidHi, hidLo, keyHi, keyLo, cvHi, cvLo,
        WqHi, WqLo, WkHi, WkLo, WvHi, WvLo,
        bq, bk, bv, qHi, qLo, kHi, kLo, vHi, vLo);

    scores_mma<<<dim3(32, 128), 256, SC_SMEM>>>(qHi, qLo, kHi, kLo, attnp);

    ctx_mma<<<dim3(8, 128), 256, 55296>>>(attnp, vHi, vLo, ctxHi, ctxLo);

    hgemm_out<<<dim3(8, 64), 256, 2 * HG_ST>>>(ctxHi, ctxLo, WoHi, WoLo, bo, outp);
}

// round 16
// speedup vs baseline: 1.0420x; 1.0116x over previous
#include <cuda_runtime.h>
#include <cuda_bf16.h>
#include <cstdint>

#define B_  8
#define L_  1024
#define D_  1024
#define H_  16
#define DK_ 64
#define M_  (B_*L_)   // 8192

// ---------------- scratch (device globals) ----------------
__device__ __nv_bfloat16 g_qHi[M_*D_], g_qLo[M_*D_];   // [B,H,L,64]
__device__ __nv_bfloat16 g_kHi[M_*D_], g_kLo[M_*D_];
__device__ __nv_bfloat16 g_vHi[M_*D_], g_vLo[M_*D_];
__device__ float g_attn[134217728];
__device__ float g_outs[M_*D_];
__device__ __nv_bfloat16 g_hidHi[M_*D_], g_hidLo[M_*D_];
__device__ __nv_bfloat16 g_keyHi[M_*D_], g_keyLo[M_*D_];
__device__ __nv_bfloat16 g_cvHi [M_*D_], g_cvLo [M_*D_];
__device__ __nv_bfloat16 g_ctxHi[M_*D_], g_ctxLo[M_*D_];
__device__ __nv_bfloat16 g_WqHi[D_*D_], g_WqLo[D_*D_];
__device__ __nv_bfloat16 g_WkHi[D_*D_], g_WkLo[D_*D_];
__device__ __nv_bfloat16 g_WvHi[D_*D_], g_WvLo[D_*D_];
__device__ __nv_bfloat16 g_WoHi[D_*D_], g_WoLo[D_*D_];

// ---------------- helpers ----------------
__device__ __forceinline__ uint32_t smem_u32(const void* p) {
    return (uint32_t)__cvta_generic_to_shared((void*)p);
}
#define CP_COMMIT() asm volatile("cp.async.commit_group;" ::: "memory")
#define CP_WAIT0()  asm volatile("cp.async.wait_group 0;" ::: "memory")
#define CP_WAIT1()  asm volatile("cp.async.wait_group 1;" ::: "memory")
__device__ __forceinline__ void cp16(uint32_t dst, const void* src) {
    asm volatile("cp.async.cg.shared.global [%0], [%1], 16;" :: "r"(dst), "l"(src));
}
__device__ __forceinline__ void ldsm4(uint32_t* r, uint32_t a) {
    asm volatile("ldmatrix.sync.aligned.m8n8.x4.shared.b16 {%0,%1,%2,%3}, [%4];"
        : "=r"(r[0]), "=r"(r[1]), "=r"(r[2]), "=r"(r[3]) : "r"(a));
}
__device__ __forceinline__ void ldsm4t(uint32_t* r, uint32_t a) {
    asm volatile("ldmatrix.sync.aligned.m8n8.x4.trans.shared.b16 {%0,%1,%2,%3}, [%4];"
        : "=r"(r[0]), "=r"(r[1]), "=r"(r[2]), "=r"(r[3]) : "r"(a));
}
__device__ __forceinline__ void mma_bf16(float* c, const uint32_t* a, const uint32_t* b) {
    asm volatile("mma.sync.aligned.m16n8k16.row.col.f32.bf16.bf16.f32 "
        "{%0,%1,%2,%3}, {%4,%5,%6,%7}, {%8,%9}, {%0,%1,%2,%3};"
        : "+f"(c[0]), "+f"(c[1]), "+f"(c[2]), "+f"(c[3])
        : "r"(a[0]), "r"(a[1]), "r"(a[2]), "r"(a[3]), "r"(b[0]), "r"(b[1]));
}
__device__ __forceinline__ void hilo_pack(float a, float b, uint32_t& hi, uint32_t& lo) {
    __nv_bfloat16 ha = __float2bfloat16(a), hb = __float2bfloat16(b);
    __nv_bfloat16 la = __float2bfloat16(a - __bfloat162float(ha));
    __nv_bfloat16 lb = __float2bfloat16(b - __bfloat162float(hb));
    hi = (uint32_t)__bfloat16_as_ushort(ha) | ((uint32_t)__bfloat16_as_ushort(hb) << 16);
    lo = (uint32_t)__bfloat16_as_ushort(la) | ((uint32_t)__bfloat16_as_ushort(lb) << 16);
}

// ---------------- prep: fp32 -> bf16 hi/lo (batched) ----------------
struct __align__(8) bf4 { __nv_bfloat16 x, y, z, w; };
__global__ void split3_kernel(const float4* __restrict__ X0, const float4* __restrict__ X1,
                              const float4* __restrict__ X2,
                              bf4* __restrict__ H0, bf4* __restrict__ L0,
                              bf4* __restrict__ H1, bf4* __restrict__ L1,
                              bf4* __restrict__ H2, bf4* __restrict__ L2, int n4)
{
    const float4* X; bf4 *Hi, *Lo;
    if (blockIdx.y == 0)      { X = X0; Hi = H0; Lo = L0; }
    else if (blockIdx.y == 1) { X = X1; Hi = H1; Lo = L1; }
    else                      { X = X2; Hi = H2; Lo = L2; }
    int i = blockIdx.x * 256 + threadIdx.x;
    if (i >= n4) return;
    float4 v = X[i];
    bf4 h, l;
    h.x = __float2bfloat16(v.x); l.x = __float2bfloat16(v.x - __bfloat162float(h.x));
    h.y = __float2bfloat16(v.y); l.y = __float2bfloat16(v.y - __bfloat162float(h.y));
    h.z = __float2bfloat16(v.z); l.z = __float2bfloat16(v.z - __bfloat162float(h.z));
    h.w = __float2bfloat16(v.w); l.w = __float2bfloat16(v.w - __bfloat162float(h.w));
    Hi[i] = h; Lo[i] = l;
}
__global__ void tsplit4_kernel(const float* __restrict__ W0, const float* __restrict__ W1,
                               const float* __restrict__ W2, const float* __restrict__ W3,
                               __nv_bfloat16* __restrict__ H0, __nv_bfloat16* __restrict__ L0,
                               __nv_bfloat16* __restrict__ H1, __nv_bfloat16* __restrict__ L1,
                               __nv_bfloat16* __restrict__ H2, __nv_bfloat16* __restrict__ L2,
                               __nv_bfloat16* __restrict__ H3, __nv_bfloat16* __restrict__ L3)
{
    const float* W; __nv_bfloat16 *Hi, *Lo;
    int z = blockIdx.z;
    if (z == 0)      { W = W0; Hi = H0; Lo = L0; }
    else if (z == 1) { W = W1; Hi = H1; Lo = L1; }
    else if (z == 2) { W = W2; Hi = H2; Lo = L2; }
    else             { W = W3; Hi = H3; Lo = L3; }
    __shared__ float t[32][33];
    int bx = blockIdx.x * 32, by = blockIdx.y * 32;
    int x = threadIdx.x, y = threadIdx.y;
#pragma unroll
    for (int i = 0; i < 32; i += 8)
        t[y + i][x] = W[(size_t)(by + y + i) * D_ + bx + x];
    __syncthreads();
#pragma unroll
    for (int i = 0; i < 32; i += 8) {
        float v = t[x][y + i];
        __nv_bfloat16 h = __float2bfloat16(v);
        __nv_bfloat16 l = __float2bfloat16(v - __bfloat162float(h));
        size_t o = (size_t)(bx + y + i) * D_ + by + x;
        Hi[o] = h; Lo[o] = l;
    }
}

// ---------------- HMMA GEMM: 128x128 tile, 256 threads ----------------
#define HG_ST 40960u
template <int MODE>
__device__ __forceinline__
void hgemm_body(const __nv_bfloat16* __restrict__ AHi, const __nv_bfloat16* __restrict__ ALo,
                const __nv_bfloat16* __restrict__ BHi, const __nv_bfloat16* __restrict__ BLo,
                const float* __restrict__ bias,
                float* __restrict__ C, __nv_bfloat16* __restrict__ CHi, __nv_bfloat16* __restrict__ CLo,
                char* smc)
{
    const int tid = threadIdx.x, lane = tid & 31, wid = tid >> 5;
    const int wm = wid >> 2, wn = wid & 3;
    const int n0 = blockIdx.x * 128, m0 = blockIdx.y * 128;
    const uint32_t sb = smem_u32(smc);

    const int lr = tid >> 2, lc = tid & 3;
    const int arow = wm * 64 + (lane & 15);
    const uint32_t akb = (lane >> 4) * 16;
    const int bn8 = (lane & 16) ? 8 : 0;
    const uint32_t bkh = (lane & 8) ? 16 : 0;
    const int br = lane & 7;

    float acc[4][4][4];
#pragma unroll
    for (int i = 0; i < 4; i++)
#pragma unroll
        for (int j = 0; j < 4; j++)
#pragma unroll
            for (int q = 0; q < 4; q++) acc[i][j][q] = 0.f;

    auto load_stage = [&](int s, int buf) {
        uint32_t base = sb + buf * HG_ST;
        int k0 = s * 32;
#pragma unroll
        for (int half = 0; half < 2; half++) {
            int row = lr + half * 64;
            uint32_t doff = row * 80 + lc * 16;
            cp16(base + doff,          AHi + (size_t)(m0 + row) * D_ + k0 + lc * 8);
            cp16(base + 10240 + doff,  ALo + (size_t)(m0 + row) * D_ + k0 + lc * 8);
            cp16(base + 20480 + doff,  BHi + (size_t)(n0 + row) * D_ + k0 + lc * 8);
            cp16(base + 30720 + doff,  BLo + (size_t)(n0 + row) * D_ + k0 + lc * 8);
        }
    };

    load_stage(0, 0); CP_COMMIT();

    for (int s = 0; s < 32; s++) {
        if (s < 31) { load_stage(s + 1, (s + 1) & 1); CP_COMMIT(); CP_WAIT1(); }
        else        { CP_WAIT0(); }
        __syncthreads();
        uint32_t aHiB = sb + (s & 1) * HG_ST;
        uint32_t aLoB = aHiB + 10240, bHiB = aHiB + 20480, bLoB = aHiB + 30720;
#pragma unroll
        for (int h = 0; h < 2; h++) {
            uint32_t bhi[2][4], blo[2][4];
#pragma unroll
            for (int g = 0; g < 2; g++) {
                uint32_t ba = (uint32_t)(wn * 32 + g * 16 + bn8 + br) * 80 + h * 32 + bkh;
                ldsm4(bhi[g], bHiB + ba);
                ldsm4(blo[g], bLoB + ba);
            }
#pragma unroll
            for (int mf = 0; mf < 4; mf++) {
                uint32_t ah[4], al[4];
                uint32_t aa = (uint32_t)(arow + mf * 16) * 80 + h * 32 + akb;
                ldsm4(ah, aHiB + aa);
                ldsm4(al, aLoB + aa);
#pragma unroll
                for (int g = 0; g < 2; g++)
#pragma unroll
                    for (int j = 0; j < 2; j++)
                        mma_bf16(acc[mf][g * 2 + j], ah, &bhi[g][j * 2]);
#pragma unroll
                for (int g = 0; g < 2; g++)
#pragma unroll
                    for (int j = 0; j < 2; j++)
                        mma_bf16(acc[mf][g * 2 + j], ah, &blo[g][j * 2]);
#pragma unroll
                for (int g = 0; g < 2; g++)
#pragma unroll
                    for (int j = 0; j < 2; j++)
                        mma_bf16(acc[mf][g * 2 + j], al, &bhi[g][j * 2]);
            }
        }
        __syncthreads();
    }

#pragma unroll
    for (int mf = 0; mf < 4; mf++)
#pragma unroll
        for (int nf = 0; nf < 4; nf++) {
            int col = n0 + wn * 32 + nf * 8 + (lane & 3) * 2;
            float b0 = __ldg(bias + col), b1 = __ldg(bias + col + 1);
            int r0 = m0 + wm * 64 + mf * 16 + (lane >> 2);
#pragma unroll
            for (int half = 0; half < 2; half++) {
                int r = r0 + half * 8;
                float v0 = acc[mf][nf][half * 2 + 0] + b0;
                float v1 = acc[mf][nf][half * 2 + 1] + b1;
                if (MODE == 0) {
                    *(float2*)(C + (size_t)r * D_ + col) = make_float2(v0, v1);
                } else {
                    int hh = col >> 6, d = col & 63;
                    int bb = r >> 10, l = r & 1023;
                    size_t dst = (((size_t)(bb * H_ + hh) * L_ + l) * DK_) + d;
                    uint32_t hi, lo;
                    hilo_pack(v0, v1, hi, lo);
                    *(uint32_t*)(CHi + dst) = hi;
                    *(uint32_t*)(CLo + dst) = lo;
                }
            }
        }
}

__global__ __launch_bounds__(256)
void hgemm_qkv(const __nv_bfloat16* hidHi, const __nv_bfloat16* hidLo,
               const __nv_bfloat16* keyHi, const __nv_bfloat16* keyLo,
               const __nv_bfloat16* cvHi,  const __nv_bfloat16* cvLo,
               const __nv_bfloat16* WqHi, const __nv_bfloat16* WqLo,
               const __nv_bfloat16* WkHi, const __nv_bfloat16* WkLo,
               const __nv_bfloat16* WvHi, const __nv_bfloat16* WvLo,
               const float* bq, const float* bk, const float* bv,
               __nv_bfloat16* qHi, __nv_bfloat16* qLo,
               __nv_bfloat16* kHi, __nv_bfloat16* kLo,
               __nv_bfloat16* vHi, __nv_bfloat16* vLo)
{
    extern __shared__ char smc[];
    const __nv_bfloat16 *AHi, *ALo, *BHi, *BLo;
    const float* bias;
    __nv_bfloat16 *CHi, *CLo;
    int z = blockIdx.z;
    if (z == 0)      { AHi = hidHi; ALo = hidLo; BHi = WqHi; BLo = WqLo; bias = bq; CHi = qHi; CLo = qLo; }
    else if (z == 1) { AHi = keyHi; ALo = keyLo; BHi = WkHi; BLo = WkLo; bias = bk; CHi = kHi; CLo = kLo; }
    else             { AHi = cvHi;  ALo = cvLo;  BHi = WvHi; BLo = WvLo; bias = bv; CHi = vHi; CLo = vLo; }
    hgemm_body<1>(AHi, ALo, BHi, BLo, bias, nullptr, CHi, CLo, smc);
}

__global__ __launch_bounds__(256)
void hgemm_out(const __nv_bfloat16* AHi, const __nv_bfloat16* ALo,
               const __nv_bfloat16* BHi, const __nv_bfloat16* BLo,
               const float* bias, float* C)
{
    extern __shared__ char smc[];
    hgemm_body<0>(AHi, ALo, BHi, BLo, bias, C, nullptr, nullptr, smc);
}

// ---------------- scores (Q hoisted) + softmax ----------------
#define SC_SMEM 215168u
__global__ __launch_bounds__(256)
void scores_mma(const __nv_bfloat16* __restrict__ QHi, const __nv_bfloat16* __restrict__ QLo,
                const __nv_bfloat16* __restrict__ KHi, const __nv_bfloat16* __restrict__ KLo,
                float* __restrict__ attn)
{
    extern __shared__ char smc[];
    const int tid = threadIdx.x, lane = tid & 31, wid = tid >> 5;
    const int wm = wid >> 2, wn = wid & 3;
    const int bh = blockIdx.y, q0 = blockIdx.x * 32;
    const uint32_t sb = smem_u32(smc);
    float* Ss = (float*)(smc + 82944);
    float* sinv = (float*)(smc + 215040);

    {
        int row = tid >> 3, ch = tid & 7;
        const size_t src = ((size_t)bh * L_ + q0 + row) * DK_ + ch * 8;
        cp16(sb + row * 144 + ch * 16, QHi + src);
        cp16(sb + 4608 + row * 144 + ch * 16, QLo + src);
    }
    auto loadK = [&](int cc, int buf) {
        uint32_t base = sb + 9216 + buf * 36864;
#pragma unroll
        for (int i = 0; i < 4; i++) {
            int idx = tid + i * 256;
            int row = idx >> 3, ch = idx & 7;
            const size_t src = ((size_t)bh * L_ + cc * 128 + row) * DK_ + ch * 8;
            cp16(base + row * 144 + ch * 16, KHi + src);
            cp16(base + 18432 + row * 144 + ch * 16, KLo + src);
        }
    };
    loadK(0, 0); CP_COMMIT();
    CP_WAIT0();
    __syncthreads();     // Q + K0 resident

    const uint32_t akb = (lane >> 4) * 16;
    const int bn8 = (lane & 16) ? 8 : 0;
    const uint32_t bkh = (lane & 8) ? 16 : 0;
    const int br = lane & 7;

    uint32_t qh[4][4], ql[4][4];
#pragma unroll
    for (int h = 0; h < 4; h++) {
        uint32_t aa = (uint32_t)(wm * 16 + (lane & 15)) * 144 + h * 32 + akb;
        ldsm4(qh[h], sb + aa);
        ldsm4(ql[h], sb + 4608 + aa);
    }

    for (int cc = 0; cc < 8; cc++) {
        if (cc < 7) { loadK(cc + 1, (cc + 1) & 1); CP_COMMIT(); CP_WAIT1(); }
        else        { CP_WAIT0(); }
        __syncthreads();
        uint32_t kHiB = sb + 9216 + (cc & 1) * 36864;
        uint32_t kLoB = kHiB + 18432;
        float acc[4][4];
#pragma unroll
        for (int i = 0; i < 4; i++)
#pragma unroll
            for (int q = 0; q < 4; q++) acc[i][q] = 0.f;
#pragma unroll
        for (int h = 0; h < 4; h++) {
            uint32_t bhi[2][4], blo[2][4];
#pragma unroll
            for (int g = 0; g < 2; g++) {
                uint32_t ba = (uint32_t)(wn * 32 + g * 16 + bn8 + br) * 144 + h * 32 + bkh;
                ldsm4(bhi[g], kHiB + ba);
                ldsm4(blo[g], kLoB + ba);
            }
#pragma unroll
            for (int g = 0; g < 2; g++)
#pragma unroll
                for (int j = 0; j < 2; j++)
                    mma_bf16(acc[g * 2 + j], qh[h], &bhi[g][j * 2]);
#pragma unroll
            for (int g = 0; g < 2; g++)
#pragma unroll
                for (int j = 0; j < 2; j++)
                    mma_bf16(acc[g * 2 + j], qh[h], &blo[g][j * 2]);
#pragma unroll
            for (int g = 0; g < 2; g++)
#pragma unroll
                for (int j = 0; j < 2; j++)
                    mma_bf16(acc[g * 2 + j], ql[h], &bhi[g][j * 2]);
        }
#pragma unroll
        for (int nf = 0; nf < 4; nf++) {
            int col = cc * 128 + wn * 32 + nf * 8 + (lane & 3) * 2;
            int row = wm * 16 + (lane >> 2);
            *(float2*)(Ss + (size_t)row * 1032 + col) =
                make_float2(acc[nf][0] * 0.125f, acc[nf][1] * 0.125f);
            *(float2*)(Ss + (size_t)(row + 8) * 1032 + col) =
                make_float2(acc[nf][2] * 0.125f, acc[nf][3] * 0.125f);
        }
        __syncthreads();
    }

    int r = tid >> 3, g = tid & 7;
    float m = -1e30f;
    for (int c = g; c < 1024; c += 8) m = fmaxf(m, Ss[r * 1032 + c]);
#pragma unroll
    for (int o = 4; o; o >>= 1) m = fmaxf(m, __shfl_xor_sync(0xffffffffu, m, o));
    float s = 0.f;
    for (int c = g; c < 1024; c += 8) {
        float e = __expf(Ss[r * 1032 + c] - m);
        s += e;
        Ss[r * 1032 + c] = e;
    }
#pragma unroll
    for (int o = 4; o; o >>= 1) s += __shfl_xor_sync(0xffffffffu, s, o);
    if (g == 0) sinv[r] = 1.f / s;
    __syncthreads();

    float* Ap = attn + ((size_t)bh * L_ + q0) * L_;
    for (int idx = tid; idx < 32 * 1024 / 4; idx += 256) {
        int rr = idx >> 8, c4 = idx & 255;
        float inv = sinv[rr];
        float4 v;
        v.x = Ss[rr * 1032 + c4 * 4 + 0] * inv;
        v.y = Ss[rr * 1032 + c4 * 4 + 1] * inv;
        v.z = Ss[rr * 1032 + c4 * 4 + 2] * inv;
        v.w = Ss[rr * 1032 + c4 * 4 + 3] * inv;
        ((float4*)Ap)[idx] = v;
    }
}

// ---------------- ctx = attn @ V: fp32 P staged via cp.async (latency hidden) ----------------
// smem: Phi 0 (128*144=18432) | Plo 18432 | V buf0 @36864 (hi 9216 | lo 9216)
//       V buf1 @55296 | Pf32 @73728 (128 rows x 272B) ; total 108544
#define CX_V0   36864u
#define CX_V1   55296u
#define CX_PF   73728u
#define CX_PSTR 272u
#define CTX_SMEM 108544u
__global__ __launch_bounds__(256)
void ctx_mma(const float* __restrict__ attn,
             const __nv_bfloat16* __restrict__ VHi, const __nv_bfloat16* __restrict__ VLo,
             __nv_bfloat16* __restrict__ CHi, __nv_bfloat16* __restrict__ CLo)
{
    extern __shared__ char smc[];
    const int tid = threadIdx.x, lane = tid & 31, wid = tid >> 5;
    const int wm = wid >> 1, wn = wid & 1;
    const int bh = blockIdx.y, q0 = blockIdx.x * 128;
    const int b = bh >> 4, hh = bh & 15;
    const uint32_t sb = smem_u32(smc);

    float acc[2][4][4];
#pragma unroll
    for (int i = 0; i < 2; i++)
#pragma unroll
        for (int j = 0; j < 4; j++)
#pragma unroll
            for (int q = 0; q < 4; q++) acc[i][j][q] = 0.f;

    const uint32_t akb = (lane >> 4) * 16;
    const int vkoff = ((lane & 8) ? 8 : 0) + (lane & 7);
    const int vdoff = (lane & 16) ? 8 : 0;

    auto loadV = [&](int c, int buf) {
        uint32_t base = sb + (buf ? CX_V1 : CX_V0);
        int k0 = c * 64;
#pragma unroll
        for (int i = 0; i < 2; i++) {
            int idx = tid + i * 256;
            int row = idx >> 3, ch = idx & 7;
            const size_t src = ((size_t)bh * L_ + k0 + row) * DK_ + ch * 8;
            cp16(base + row * 144 + ch * 16, VHi + src);
            cp16(base + 9216 + row * 144 + ch * 16, VLo + src);
        }
    };
    auto loadP = [&](int c) {
        int k0 = c * 64;
#pragma unroll
        for (int i = 0; i < 8; i++) {
            int idx = tid + i * 256;
            int row = idx >> 4, ch = idx & 15;
            cp16(sb + CX_PF + row * CX_PSTR + ch * 16,
                 attn + ((size_t)bh * L_ + q0 + row) * L_ + k0 + ch * 4);
        }
    };

    loadV(0, 0);
    loadP(0);
    CP_COMMIT();

    for (int c = 0; c < 16; c++) {
        CP_WAIT0();
        __syncthreads();               // P(c), V(c) visible; staging free (MMA c-1 done)

        // convert Pf32 (smem) -> bf16 hi/lo staging
#pragma unroll
        for (int i = 0; i < 4; i++) {
            int task = tid + i * 256;
            int rr = task >> 3, ch = task & 7;
            const float* p = (const float*)(smc + CX_PF + rr * CX_PSTR + ch * 32);
            float4 v0 = *(const float4*)p;
            float4 v1 = *(const float4*)(p + 4);
            uint4 hi, lo;
            hilo_pack(v0.x, v0.y, hi.x, lo.x);
            hilo_pack(v0.z, v0.w, hi.y, lo.y);
            hilo_pack(v1.x, v1.y, hi.z, lo.z);
            hilo_pack(v1.z, v1.w, hi.w, lo.w);
            *(uint4*)(smc + rr * 144 + ch * 16) = hi;
            *(uint4*)(smc + 18432 + rr * 144 + ch * 16) = lo;
        }
        __syncthreads();               // staging ready; Pf32 consumed

        if (c < 15) {                  // next chunk's loads overlap this MMA
            loadV(c + 1, (c + 1) & 1);
            loadP(c + 1);
            CP_COMMIT();
        }

        uint32_t vHiB = sb + ((c & 1) ? CX_V1 : CX_V0);
        uint32_t vLoB = vHiB + 9216;
#pragma unroll
        for (int h = 0; h < 4; h++) {
            uint32_t vhi[2][4], vlo[2][4];
#pragma unroll
            for (int g = 0; g < 2; g++) {
                uint32_t va = (uint32_t)(h * 16 + vkoff) * 144
                            + (uint32_t)(wn * 32 + g * 16 + vdoff) * 2;
                ldsm4t(vhi[g], vHiB + va);
                ldsm4t(vlo[g], vLoB + va);
            }
#pragma unroll
            for (int mf = 0; mf < 2; mf++) {
                uint32_t ah[4], al[4];
                uint32_t aa = (uint32_t)(wm * 32 + mf * 16 + (lane & 15)) * 144 + h * 32 + akb;
                ldsm4(ah, sb + aa);
                ldsm4(al, sb + 18432 + aa);
#pragma unroll
                for (int g = 0; g < 2; g++)
#pragma unroll
                    for (int j = 0; j < 2; j++)
                        mma_bf16(acc[mf][g * 2 + j], ah, &vhi[g][j * 2]);
#pragma unroll
                for (int g = 0; g < 2; g++)
#pragma unroll
                    for (int j = 0; j < 2; j++)
                        mma_bf16(acc[mf][g * 2 + j], ah, &vlo[g][j * 2]);
#pragma unroll
                for (int g = 0; g < 2; g++)
#pragma unroll
                    for (int j = 0; j < 2; j++)
                        mma_bf16(acc[mf][g * 2 + j], al, &vhi[g][j * 2]);
            }
        }
        __syncthreads();               // staging/V(c) free for reuse
    }

#pragma unroll
    for (int mf = 0; mf < 2; mf++)
#pragma unroll
        for (int nf = 0; nf < 4; nf++) {
            int d = wn * 32 + nf * 8 + (lane & 3) * 2;
            int q = q0 + wm * 32 + mf * 16 + (lane >> 2);
#pragma unroll
            for (int half = 0; half < 2; half++) {
                int qq = q + half * 8;
                size_t dst = ((size_t)(b * L_ + qq)) * D_ + hh * DK_ + d;
                uint32_t hi, lo;
                hilo_pack(acc[mf][nf][half * 2 + 0], acc[mf][nf][half * 2 + 1], hi, lo);
                *(uint32_t*)(CHi + dst) = hi;
                *(uint32_t*)(CLo + dst) = lo;
            }
        }
}

// ---------------------------------------------------------------------------
extern "C" void kernel_launch(void* const* d_in, const int* in_sizes, int n_in,
                              void* d_out, int out_size)
{
    const float* hidden = (const float*)d_in[0];
    const float* key    = (const float*)d_in[1];
    const float* ctxv   = (const float*)d_in[2];
    const float* Wq = (const float*)d_in[3];
    const float* bq = (const float*)d_in[4];
    const float* Wk = (const float*)d_in[5];
    const float* bk = (const float*)d_in[6];
    const float* Wv = (const float*)d_in[7];
    const float* bv = (const float*)d_in[8];
    const float* Wo = (const float*)d_in[9];
    const float* bo = (const float*)d_in[10];

    float *ap, *op;
    cudaGetSymbolAddress((void**)&ap, g_attn);
    cudaGetSymbolAddress((void**)&op, g_outs);
    __nv_bfloat16 *qHi,*qLo,*kHi,*kLo,*vHi,*vLo;
    cudaGetSymbolAddress((void**)&qHi, g_qHi); cudaGetSymbolAddress((void**)&qLo, g_qLo);
    cudaGetSymbolAddress((void**)&kHi, g_kHi); cudaGetSymbolAddress((void**)&kLo, g_kLo);
    cudaGetSymbolAddress((void**)&vHi, g_vHi); cudaGetSymbolAddress((void**)&vLo, g_vLo);
    __nv_bfloat16 *hidHi,*hidLo,*keyHi,*keyLo,*cvHi,*cvLo,*ctxHi,*ctxLo;
    cudaGetSymbolAddress((void**)&hidHi, g_hidHi); cudaGetSymbolAddress((void**)&hidLo, g_hidLo);
    cudaGetSymbolAddress((void**)&keyHi, g_keyHi); cudaGetSymbolAddress((void**)&keyLo, g_keyLo);
    cudaGetSymbolAddress((void**)&cvHi,  g_cvHi);  cudaGetSymbolAddress((void**)&cvLo,  g_cvLo);
    cudaGetSymbolAddress((void**)&ctxHi, g_ctxHi); cudaGetSymbolAddress((void**)&ctxLo, g_ctxLo);
    __nv_bfloat16 *WqHi,*WqLo,*WkHi,*WkLo,*WvHi,*WvLo,*WoHi,*WoLo;
    cudaGetSymbolAddress((void**)&WqHi, g_WqHi); cudaGetSymbolAddress((void**)&WqLo, g_WqLo);
    cudaGetSymbolAddress((void**)&WkHi, g_WkHi); cudaGetSymbolAddress((void**)&WkLo, g_WkLo);
    cudaGetSymbolAddress((void**)&WvHi, g_WvHi); cudaGetSymbolAddress((void**)&WvLo, g_WvLo);
    cudaGetSymbolAddress((void**)&WoHi, g_WoHi); cudaGetSymbolAddress((void**)&WoLo, g_WoLo);

    const size_t out_elems  = (size_t)B_ * L_ * D_;
    const size_t attn_elems = (size_t)B_ * H_ * L_ * L_;
    float* outp;
    float* attnp;
    if ((size_t)out_size >= out_elems + attn_elems) {
        outp  = (float*)d_out;
        attnp = (float*)d_out + out_elems;
    } else if ((size_t)out_size == attn_elems) {
        outp  = op;
        attnp = (float*)d_out;
    } else {
        outp  = (float*)d_out;
        attnp = ap;
    }

    cudaFuncSetAttribute(hgemm_qkv, cudaFuncAttributeMaxDynamicSharedMemorySize, 2 * HG_ST);
    cudaFuncSetAttribute(hgemm_out, cudaFuncAttributeMaxDynamicSharedMemorySize, 2 * HG_ST);
    cudaFuncSetAttribute(scores_mma, cudaFuncAttributeMaxDynamicSharedMemorySize, SC_SMEM);
    cudaFuncSetAttribute(ctx_mma, cudaFuncAttributeMaxDynamicSharedMemorySize, CTX_SMEM);

    const int n4 = M_ * D_ / 4;
    split3_kernel<<<dim3(n4 / 256, 3), 256>>>(
        (const float4*)hidden, (const float4*)key, (const float4*)ctxv,
        (bf4*)hidHi, (bf4*)hidLo, (bf4*)keyHi, (bf4*)keyLo, (bf4*)cvHi, (bf4*)cvLo, n4);
    tsplit4_kernel<<<dim3(32, 32, 4), dim3(32, 8)>>>(
        Wq, Wk, Wv, Wo, WqHi, WqLo, WkHi, WkLo, WvHi, WvLo, WoHi, WoLo);

    hgemm_qkv<<<dim3(8, 64, 3), 256, 2 * HG_ST>>>(
        hidHi, hidLo, keyHi, keyLo, cvHi, cvLo,
        WqHi, WqLo, WkHi, WkLo, WvHi, WvLo,
        bq, bk, bv, qHi, qLo, kHi, kLo, vHi, vLo);

    scores_mma<<<dim3(32, 128), 256, SC_SMEM>>>(qHi, qLo, kHi, kLo, attnp);

    ctx_mma<<<dim3(8, 128), 256, CTX_SMEM>>>(attnp, vHi, vLo, ctxHi, ctxLo);

    hgemm_out<<<dim3(8, 64), 256, 2 * HG_ST>>>(ctxHi, ctxLo, WoHi, WoLo, bo, outp);
}